// round 4
// baseline (speedup 1.0000x reference)
#include <cuda_runtime.h>
#include <math.h>

#define Bb   8
#define Ss   1024
#define Dd   768
#define Hh   12
#define HDh  64
#define DFF  3072
#define LL   6

// ---------------- scratch ----------------
__device__ float gX  [Bb*Ss*Dd];
__device__ float gXr [Bb*Ss*Dd];          // tf32-rounded copy of X
__device__ float gQ  [Bb*Ss*Dd];
__device__ float gK  [Bb*Ss*Dd];
__device__ float gV  [Bb*Ss*Dd];
__device__ float gS  [100663296];         // B*H*S*S scores (402 MB)
__device__ float gHb [Bb*Ss*Dd];
__device__ float gY1 [Bb*Ss*Dd];
__device__ float gY1r[Bb*Ss*Dd];
__device__ float gF  [Bb*Ss*DFF];
__device__ float gWqr[LL*Dd*Dd];
__device__ float gWkr[LL*Dd*Dd];
__device__ float gWvr[LL*Dd*Dd];
__device__ float gW1r[LL*DFF*Dd];
__device__ float gW2r[LL*Dd*DFF];

// ---------------- helpers ----------------
__device__ __forceinline__ float f2tf32f(float f) {
    unsigned u;
    asm("cvt.rna.tf32.f32 %0, %1;" : "=r"(u) : "f"(f));
    return __uint_as_float(u);
}

__device__ __forceinline__ void mma_tf32(float c[4], unsigned a0, unsigned a1, unsigned a2, unsigned a3,
                                         unsigned b0, unsigned b1) {
    asm volatile(
        "mma.sync.aligned.m16n8k8.row.col.f32.tf32.tf32.f32 "
        "{%0,%1,%2,%3}, {%4,%5,%6,%7}, {%8,%9}, {%0,%1,%2,%3};\n"
        : "+f"(c[0]), "+f"(c[1]), "+f"(c[2]), "+f"(c[3])
        : "r"(a0), "r"(a1), "r"(a2), "r"(a3), "r"(b0), "r"(b1));
}

union U8 { uint4 v[2]; unsigned u[8]; };

__device__ __forceinline__ float blockReduceSum(float v) {
    __shared__ float red[32];
    #pragma unroll
    for (int o = 16; o > 0; o >>= 1) v += __shfl_xor_sync(0xffffffffu, v, o);
    int lane = threadIdx.x & 31, w = threadIdx.x >> 5;
    if (lane == 0) red[w] = v;
    __syncthreads();
    v = (threadIdx.x < 8) ? red[threadIdx.x] : 0.f;
    if (w == 0) {
        #pragma unroll
        for (int o = 4; o > 0; o >>= 1) v += __shfl_xor_sync(0xffffffffu, v, o);
        if (lane == 0) red[0] = v;
    }
    __syncthreads();
    float r = red[0];
    __syncthreads();
    return r;
}

__device__ __forceinline__ float blockReduceMax(float v) {
    __shared__ float red[32];
    #pragma unroll
    for (int o = 16; o > 0; o >>= 1) v = fmaxf(v, __shfl_xor_sync(0xffffffffu, v, o));
    int lane = threadIdx.x & 31, w = threadIdx.x >> 5;
    if (lane == 0) red[w] = v;
    __syncthreads();
    v = (threadIdx.x < 8) ? red[threadIdx.x] : -3.4e38f;
    if (w == 0) {
        #pragma unroll
        for (int o = 4; o > 0; o >>= 1) v = fmaxf(v, __shfl_xor_sync(0xffffffffu, v, o));
        if (lane == 0) red[0] = v;
    }
    __syncthreads();
    float r = red[0];
    __syncthreads();
    return r;
}

// ---------------- tf32 rounding pass (weights, once per launch) ----------------
__global__ void round_kernel(float* __restrict__ dst, const float* __restrict__ src) {
    int i = blockIdx.x * blockDim.x + threadIdx.x;
    float4 v = ((const float4*)src)[i];
    v.x = f2tf32f(v.x); v.y = f2tf32f(v.y); v.z = f2tf32f(v.z); v.w = f2tf32f(v.w);
    ((float4*)dst)[i] = v;
}

// ---------------- embedding (+ rounded copy) ----------------
__global__ void embed_kernel(const int* __restrict__ ids, const float* __restrict__ emb,
                             const float* __restrict__ pe, float* __restrict__ x,
                             float* __restrict__ xr) {
    int i  = blockIdx.x * blockDim.x + threadIdx.x;
    int d  = i % Dd;
    int bs = i / Dd;
    int s  = bs % Ss;
    float v = emb[(size_t)ids[bs] * Dd + d] + pe[(size_t)s * Dd + d];
    x[i]  = v;
    xr[i] = f2tf32f(v);
}

// ============ TF32 NT GEMM: C = A[M,K] @ B[N,K]^T (*scale, +bias, relu, round) ============
// Inputs MUST already be tf32-rounded (mainloop is a pure bit copy).
// BM=128, BN=128, BK=32, 256 threads, warp tiles 64x32, single smem buffer, 2 CTA/SM.
// k-permuted smem layout: slot = (k&3)*8 + (k>>2)  ->  LDS.128 fragment loads.
template<bool BIAS, bool RELU, bool ROUND>
__global__ __launch_bounds__(256, 2) void gemm_tf32_nt(
    int M, int N, int K,
    const float* __restrict__ A, int lda, long az,
    const float* __restrict__ B, int ldb, long bz,
    float* __restrict__ C, int ldc, long cz,
    const float* __restrict__ bias, float scale)
{
    __shared__ unsigned As[128 * 36];
    __shared__ unsigned Bs[128 * 36];

    const int z = blockIdx.z;
    const unsigned* Ap = (const unsigned*)(A + (size_t)az * z + (size_t)(blockIdx.y * 128) * lda);
    const unsigned* Bp = (const unsigned*)(B + (size_t)bz * z + (size_t)(blockIdx.x * 128) * ldb);
    const int tid = threadIdx.x;
    const int lane = tid & 31, warp = tid >> 5;
    const int wm = (warp >> 2) * 64, wn = (warp & 3) * 32;
    const int grp = lane >> 2, tig = lane & 3;
    const int lrow = tid >> 3;            // 0..31
    const int lc4  = (tid & 7) * 4;       // 0..28

    uint4 ra[4], rb[4];
    float acc[4][4][4] = {};

    auto LDG = [&](int k0) {
        #pragma unroll
        for (int p = 0; p < 4; p++) {
            ra[p] = *(const uint4*)(Ap + (size_t)(lrow + p * 32) * lda + k0 + lc4);
            rb[p] = *(const uint4*)(Bp + (size_t)(lrow + p * 32) * ldb + k0 + lc4);
        }
    };
    auto STS = [&]() {
        #pragma unroll
        for (int p = 0; p < 4; p++) {
            int base = (lrow + p * 32) * 36 + (lc4 >> 2);
            As[base + 0]  = ra[p].x;
            As[base + 8]  = ra[p].y;
            As[base + 16] = ra[p].z;
            As[base + 24] = ra[p].w;
            Bs[base + 0]  = rb[p].x;
            Bs[base + 8]  = rb[p].y;
            Bs[base + 16] = rb[p].z;
            Bs[base + 24] = rb[p].w;
        }
    };
    auto COMPUTE = [&]() {
        U8 af[4][2], bf[4];
        #pragma unroll
        for (int mi = 0; mi < 4; mi++) {
            int r = wm + mi * 16 + grp;
            af[mi][0].v[0] = *(const uint4*)(As + r * 36 + tig * 8);
            af[mi][0].v[1] = *(const uint4*)(As + r * 36 + tig * 8 + 4);
            af[mi][1].v[0] = *(const uint4*)(As + (r + 8) * 36 + tig * 8);
            af[mi][1].v[1] = *(const uint4*)(As + (r + 8) * 36 + tig * 8 + 4);
        }
        #pragma unroll
        for (int ni = 0; ni < 4; ni++) {
            int nb = wn + ni * 8 + grp;
            bf[ni].v[0] = *(const uint4*)(Bs + nb * 36 + tig * 8);
            bf[ni].v[1] = *(const uint4*)(Bs + nb * 36 + tig * 8 + 4);
        }
        #pragma unroll
        for (int kk = 0; kk < 4; kk++)
            #pragma unroll
            for (int mi = 0; mi < 4; mi++)
                #pragma unroll
                for (int ni = 0; ni < 4; ni++)
                    mma_tf32(acc[mi][ni],
                             af[mi][0].u[2 * kk], af[mi][1].u[2 * kk],
                             af[mi][0].u[2 * kk + 1], af[mi][1].u[2 * kk + 1],
                             bf[ni].u[2 * kk], bf[ni].u[2 * kk + 1]);
    };

    const int nk = K >> 5;
    LDG(0);
    STS();
    __syncthreads();

    for (int i = 0; i < nk; i++) {
        if (i + 1 < nk) LDG((i + 1) << 5);
        COMPUTE();
        if (i + 1 < nk) {
            __syncthreads();
            STS();
            __syncthreads();
        }
    }

    float* Cp = C + (size_t)cz * z;
    #pragma unroll
    for (int mi = 0; mi < 4; mi++) {
        int row = blockIdx.y * 128 + wm + mi * 16 + grp;
        #pragma unroll
        for (int ni = 0; ni < 4; ni++) {
            int col = blockIdx.x * 128 + wn + ni * 8 + 2 * tig;
            float b0 = 0.f, b1 = 0.f;
            if (BIAS) { b0 = bias[col]; b1 = bias[col + 1]; }
            float v0 = acc[mi][ni][0] * scale + b0;
            float v1 = acc[mi][ni][1] * scale + b1;
            float v2 = acc[mi][ni][2] * scale + b0;
            float v3 = acc[mi][ni][3] * scale + b1;
            if (RELU)  { v0 = fmaxf(v0, 0.f); v1 = fmaxf(v1, 0.f); v2 = fmaxf(v2, 0.f); v3 = fmaxf(v3, 0.f); }
            if (ROUND) { v0 = f2tf32f(v0); v1 = f2tf32f(v1); v2 = f2tf32f(v2); v3 = f2tf32f(v3); }
            *(float2*)(Cp + (size_t)row * ldc + col)       = make_float2(v0, v1);
            *(float2*)(Cp + (size_t)(row + 8) * ldc + col) = make_float2(v2, v3);
        }
    }
}

// ============ TF32 NN GEMM: O = att @ V (M=1024, N=64, K=1024 per bh) ============
// Inputs already tf32-rounded. BM=128, BN=64, BK=32, warp tiles 64x16.
__global__ __launch_bounds__(256, 2) void gemm_av_tf32(
    const float* __restrict__ S, const float* __restrict__ V, float* __restrict__ O)
{
    __shared__ unsigned As[128 * 36];
    __shared__ unsigned Bs[64 * 36];

    const int z = blockIdx.z;
    const unsigned* Ap = (const unsigned*)(S + (size_t)z * Ss * Ss + (size_t)(blockIdx.y * 128) * Ss);
    const unsigned* Bp = (const unsigned*)(V + (size_t)z * Ss * HDh);
    const int tid = threadIdx.x;
    const int lane = tid & 31, warp = tid >> 5;
    const int wm = (warp >> 2) * 64, wn = (warp & 3) * 16;
    const int grp = lane >> 2, tig = lane & 3;
    const int lrow = tid >> 3;            // 0..31
    const int lc4  = (tid & 7) * 4;
    const int cB = tid >> 6;              // k-class 0..3
    const int nB = tid & 63;              // column 0..63

    uint4 ra[4];
    unsigned vb[8];
    float acc[4][2][4] = {};

    auto LDG = [&](int k0) {
        #pragma unroll
        for (int p = 0; p < 4; p++)
            ra[p] = *(const uint4*)(Ap + (size_t)(lrow + p * 32) * Ss + k0 + lc4);
        #pragma unroll
        for (int t = 0; t < 8; t++)
            vb[t] = Bp[(size_t)(k0 + cB + 4 * t) * HDh + nB];
    };
    auto STS = [&]() {
        #pragma unroll
        for (int p = 0; p < 4; p++) {
            int base = (lrow + p * 32) * 36 + (lc4 >> 2);
            As[base + 0]  = ra[p].x;
            As[base + 8]  = ra[p].y;
            As[base + 16] = ra[p].z;
            As[base + 24] = ra[p].w;
        }
        *(uint4*)(Bs + nB * 36 + cB * 8)     = make_uint4(vb[0], vb[1], vb[2], vb[3]);
        *(uint4*)(Bs + nB * 36 + cB * 8 + 4) = make_uint4(vb[4], vb[5], vb[6], vb[7]);
    };
    auto COMPUTE = [&]() {
        U8 af[4][2], bf[2];
        #pragma unroll
        for (int mi = 0; mi < 4; mi++) {
            int r = wm + mi * 16 + grp;
            af[mi][0].v[0] = *(const uint4*)(As + r * 36 + tig * 8);
            af[mi][0].v[1] = *(const uint4*)(As + r * 36 + tig * 8 + 4);
            af[mi][1].v[0] = *(const uint4*)(As + (r + 8) * 36 + tig * 8);
            af[mi][1].v[1] = *(const uint4*)(As + (r + 8) * 36 + tig * 8 + 4);
        }
        #pragma unroll
        for (int ni = 0; ni < 2; ni++) {
            int nb = wn + ni * 8 + grp;
            bf[ni].v[0] = *(const uint4*)(Bs + nb * 36 + tig * 8);
            bf[ni].v[1] = *(const uint4*)(Bs + nb * 36 + tig * 8 + 4);
        }
        #pragma unroll
        for (int kk = 0; kk < 4; kk++)
            #pragma unroll
            for (int mi = 0; mi < 4; mi++)
                #pragma unroll
                for (int ni = 0; ni < 2; ni++)
                    mma_tf32(acc[mi][ni],
                             af[mi][0].u[2 * kk], af[mi][1].u[2 * kk],
                             af[mi][0].u[2 * kk + 1], af[mi][1].u[2 * kk + 1],
                             bf[ni].u[2 * kk], bf[ni].u[2 * kk + 1]);
    };

    const int nk = Ss >> 5;   // 32
    LDG(0);
    STS();
    __syncthreads();

    for (int i = 0; i < nk; i++) {
        if (i + 1 < nk) LDG((i + 1) << 5);
        COMPUTE();
        if (i + 1 < nk) {
            __syncthreads();
            STS();
            __syncthreads();
        }
    }

    const int b = z / Hh, h = z % Hh;
    float* Op = O + (size_t)b * Ss * Dd + (size_t)h * HDh;
    #pragma unroll
    for (int mi = 0; mi < 4; mi++) {
        int row = blockIdx.y * 128 + wm + mi * 16 + grp;
        #pragma unroll
        for (int ni = 0; ni < 2; ni++) {
            int col = wn + ni * 8 + 2 * tig;
            *(float2*)(Op + (size_t)row * Dd + col)       = make_float2(acc[mi][ni][0], acc[mi][ni][1]);
            *(float2*)(Op + (size_t)(row + 8) * Dd + col) = make_float2(acc[mi][ni][2], acc[mi][ni][3]);
        }
    }
}

// ---------------- softmax over rows of 1024 (emits tf32-rounded probs) ----------------
__global__ __launch_bounds__(256) void softmax_kernel(float* __restrict__ Sb) {
    float* p = Sb + (size_t)blockIdx.x * Ss;
    float4 v = ((float4*)p)[threadIdx.x];
    float m = fmaxf(fmaxf(v.x, v.y), fmaxf(v.z, v.w));
    m = blockReduceMax(m);
    float e0 = __expf(v.x - m), e1 = __expf(v.y - m), e2 = __expf(v.z - m), e3 = __expf(v.w - m);
    float s = blockReduceSum(e0 + e1 + e2 + e3);
    float inv = 1.f / s;
    float4 o = {f2tf32f(e0 * inv), f2tf32f(e1 * inv), f2tf32f(e2 * inv), f2tf32f(e3 * inv)};
    ((float4*)p)[threadIdx.x] = o;
}

// ---------------- add + layernorm (+ optional rounded copy) ----------------
__global__ __launch_bounds__(256) void add_ln_kernel(
    const float* __restrict__ x, const float* __restrict__ h,
    const float* __restrict__ g, const float* __restrict__ bias,
    float* __restrict__ out, float* __restrict__ outr)
{
    const size_t row = blockIdx.x;
    const float* px = x + row * Dd;
    const float* ph = h + row * Dd;
    int t = threadIdx.x;
    float v[3];
    #pragma unroll
    for (int i = 0; i < 3; i++) v[i] = px[t + i * 256] + ph[t + i * 256];
    float mu = blockReduceSum(v[0] + v[1] + v[2]) * (1.f / Dd);
    float q = 0.f;
    #pragma unroll
    for (int i = 0; i < 3; i++) { float d = v[i] - mu; q += d * d; }
    float var = blockReduceSum(q) * (1.f / Dd);
    float inv = rsqrtf(var + 1e-5f);
    float* po = out + row * Dd;
    float* pr = outr ? outr + row * Dd : nullptr;
    #pragma unroll
    for (int i = 0; i < 3; i++) {
        int c = t + i * 256;
        float o = (v[i] - mu) * inv * g[c] + bias[c];
        po[c] = o;
        if (pr) pr[c] = f2tf32f(o);
    }
}

// ---------------- host launcher ----------------
extern "C" void kernel_launch(void* const* d_in, const int* in_sizes, int n_in,
                              void* d_out, int out_size) {
    const int*   ids  = (const int*)  d_in[0];
    const float* emb  = (const float*)d_in[1];
    const float* pe   = (const float*)d_in[2];
    const float* Wq   = (const float*)d_in[3];
    const float* bq   = (const float*)d_in[4];
    const float* Wk   = (const float*)d_in[5];
    const float* bk   = (const float*)d_in[6];
    const float* Wv   = (const float*)d_in[7];
    const float* bv   = (const float*)d_in[8];
    const float* W1   = (const float*)d_in[9];
    const float* b1   = (const float*)d_in[10];
    const float* W2   = (const float*)d_in[11];
    const float* b2   = (const float*)d_in[12];
    const float* ln1g = (const float*)d_in[13];
    const float* ln1b = (const float*)d_in[14];
    const float* ln2g = (const float*)d_in[15];
    const float* ln2b = (const float*)d_in[16];

    float *X, *Xr, *Q, *K, *V, *Sb, *Hb, *Y1, *Y1r, *F;
    float *Wqr, *Wkr, *Wvr, *W1r, *W2r;
    cudaGetSymbolAddress((void**)&X,   gX);
    cudaGetSymbolAddress((void**)&Xr,  gXr);
    cudaGetSymbolAddress((void**)&Q,   gQ);
    cudaGetSymbolAddress((void**)&K,   gK);
    cudaGetSymbolAddress((void**)&V,   gV);
    cudaGetSymbolAddress((void**)&Sb,  gS);
    cudaGetSymbolAddress((void**)&Hb,  gHb);
    cudaGetSymbolAddress((void**)&Y1,  gY1);
    cudaGetSymbolAddress((void**)&Y1r, gY1r);
    cudaGetSymbolAddress((void**)&F,   gF);
    cudaGetSymbolAddress((void**)&Wqr, gWqr);
    cudaGetSymbolAddress((void**)&Wkr, gWkr);
    cudaGetSymbolAddress((void**)&Wvr, gWvr);
    cudaGetSymbolAddress((void**)&W1r, gW1r);
    cudaGetSymbolAddress((void**)&W2r, gW2r);

    const int M = Bb * Ss;   // 8192

    // one-time tf32 rounding of weights (amortized; memory-bound)
    round_kernel<<<(LL * Dd * Dd)  / 1024, 256>>>(Wqr, Wq);
    round_kernel<<<(LL * Dd * Dd)  / 1024, 256>>>(Wkr, Wk);
    round_kernel<<<(LL * Dd * Dd)  / 1024, 256>>>(Wvr, Wv);
    round_kernel<<<(LL * DFF * Dd) / 1024, 256>>>(W1r, W1);
    round_kernel<<<(LL * Dd * DFF) / 1024, 256>>>(W2r, W2);

    embed_kernel<<<(Bb * Ss * Dd) / 256, 256>>>(ids, emb, pe, X, Xr);

    for (int l = 0; l < LL; l++) {
        const float* wq = Wqr + (size_t)l * Dd * Dd;
        const float* wk = Wkr + (size_t)l * Dd * Dd;
        const float* wv = Wvr + (size_t)l * Dd * Dd;
        const float* w1 = W1r + (size_t)l * DFF * Dd;
        const float* w2 = W2r + (size_t)l * Dd * DFF;

        dim3 gQKV(Dd / 128, M / 128, 1);
        gemm_tf32_nt<true, false, true><<<gQKV, 256>>>(M, Dd, Dd, Xr, Dd, 0, wq, Dd, 0, Q, Dd, 0, bq + l * Dd, 1.f);
        gemm_tf32_nt<true, false, true><<<gQKV, 256>>>(M, Dd, Dd, Xr, Dd, 0, wk, Dd, 0, K, Dd, 0, bk + l * Dd, 1.f);
        gemm_tf32_nt<true, false, true><<<gQKV, 256>>>(M, Dd, Dd, Xr, Dd, 0, wv, Dd, 0, V, Dd, 0, bv + l * Dd, 1.f);

        gemm_tf32_nt<false, false, false><<<dim3(Ss / 128, Ss / 128, Bb * Hh), 256>>>(
            Ss, Ss, HDh, Q, HDh, (long)Ss * HDh, K, HDh, (long)Ss * HDh,
            Sb, Ss, (long)Ss * Ss, nullptr, 0.125f);

        softmax_kernel<<<Bb * Hh * Ss, 256>>>(Sb);

        gemm_av_tf32<<<dim3(1, Ss / 128, Bb * Hh), 256>>>(Sb, V, Hb);

        add_ln_kernel<<<M, 256>>>(X, Hb, ln1g + l * Dd, ln1b + l * Dd, Y1, Y1r);

        gemm_tf32_nt<true, true, true><<<dim3(DFF / 128, M / 128, 1), 256>>>(
            M, DFF, Dd, Y1r, Dd, 0, w1, Dd, 0, F, DFF, 0, b1 + l * DFF, 1.f);
        gemm_tf32_nt<true, false, false><<<dim3(Dd / 128, M / 128, 1), 256>>>(
            M, Dd, DFF, F, DFF, 0, w2, DFF, 0, Hb, Dd, 0, b2 + l * Dd, 1.f);

        float* outp = (l == LL - 1) ? (float*)d_out : X;
        float* outr = (l == LL - 1) ? nullptr : Xr;
        add_ln_kernel<<<M, 256>>>(Y1, Hb, ln2g + l * Dd, ln2b + l * Dd, outp, outr);
    }
}

// round 5
// speedup vs baseline: 1.3814x; 1.3814x over previous
#include <cuda_runtime.h>
#include <math.h>

#define Bb   8
#define Ss   1024
#define Dd   768
#define Hh   12
#define HDh  64
#define DFF  3072
#define LL   6
#define MOFF (Bb*Ss*Dd)      // 6291456, size of one of Q/K/V

// ---------------- scratch ----------------
__device__ float gX   [Bb*Ss*Dd];
__device__ float gXr  [Bb*Ss*Dd];          // tf32-rounded activations
__device__ float gQKV [3*Bb*Ss*Dd];        // fused QKV output (rounded)
__device__ float gHb  [Bb*Ss*Dd];
__device__ float gY1  [Bb*Ss*Dd];
__device__ float gY1r [Bb*Ss*Dd];
__device__ float gF   [Bb*Ss*DFF];
__device__ float gWqkv[LL*3*Dd*Dd];        // packed rounded [L][2304][768]
__device__ float gBqkv[LL*3*Dd];           // packed bias [L][2304]
__device__ float gW1r [LL*DFF*Dd];
__device__ float gW2r [LL*Dd*DFF];

// ---------------- helpers ----------------
__device__ __forceinline__ float f2tf32f(float f) {
    unsigned u;
    asm("cvt.rna.tf32.f32 %0, %1;" : "=r"(u) : "f"(f));
    return __uint_as_float(u);
}
__device__ __forceinline__ unsigned f2tf32u(float f) {
    unsigned u;
    asm("cvt.rna.tf32.f32 %0, %1;" : "=r"(u) : "f"(f));
    return u;
}

__device__ __forceinline__ void mma_tf32(float c[4], unsigned a0, unsigned a1, unsigned a2, unsigned a3,
                                         unsigned b0, unsigned b1) {
    asm volatile(
        "mma.sync.aligned.m16n8k8.row.col.f32.tf32.tf32.f32 "
        "{%0,%1,%2,%3}, {%4,%5,%6,%7}, {%8,%9}, {%0,%1,%2,%3};\n"
        : "+f"(c[0]), "+f"(c[1]), "+f"(c[2]), "+f"(c[3])
        : "r"(a0), "r"(a1), "r"(a2), "r"(a3), "r"(b0), "r"(b1));
}

__device__ __forceinline__ float blockReduceSum(float v) {
    __shared__ float red[32];
    #pragma unroll
    for (int o = 16; o > 0; o >>= 1) v += __shfl_xor_sync(0xffffffffu, v, o);
    int lane = threadIdx.x & 31, w = threadIdx.x >> 5;
    if (lane == 0) red[w] = v;
    __syncthreads();
    v = (threadIdx.x < 8) ? red[threadIdx.x] : 0.f;
    if (w == 0) {
        #pragma unroll
        for (int o = 4; o > 0; o >>= 1) v += __shfl_xor_sync(0xffffffffu, v, o);
        if (lane == 0) red[0] = v;
    }
    __syncthreads();
    float r = red[0];
    __syncthreads();
    return r;
}

// ---------------- weight prep ----------------
__global__ void pack_qkv_w(float* __restrict__ dst, const float* __restrict__ Wq,
                           const float* __restrict__ Wk, const float* __restrict__ Wv) {
    int i = blockIdx.x * blockDim.x + threadIdx.x;     // float4 over LL*2304*192
    const int perL = 2304 * 192;
    int l = i / perL, rem = i % perL;
    int row = rem / 192, c4 = rem % 192;
    const float* src = (row < 768)  ? Wq + ((size_t)l * 768 + row) * 768
                     : (row < 1536) ? Wk + ((size_t)l * 768 + row - 768) * 768
                                    : Wv + ((size_t)l * 768 + row - 1536) * 768;
    float4 v = ((const float4*)src)[c4];
    v.x = f2tf32f(v.x); v.y = f2tf32f(v.y); v.z = f2tf32f(v.z); v.w = f2tf32f(v.w);
    ((float4*)dst)[i] = v;
}

__global__ void pack_qkv_b(float* __restrict__ dst, const float* __restrict__ bq,
                           const float* __restrict__ bk, const float* __restrict__ bv) {
    int i = blockIdx.x * blockDim.x + threadIdx.x;     // LL*2304
    int l = i / 2304, n = i % 2304;
    dst[i] = (n < 768) ? bq[l * 768 + n] : (n < 1536) ? bk[l * 768 + n - 768] : bv[l * 768 + n - 1536];
}

__global__ void round_kernel(float* __restrict__ dst, const float* __restrict__ src) {
    int i = blockIdx.x * blockDim.x + threadIdx.x;
    float4 v = ((const float4*)src)[i];
    v.x = f2tf32f(v.x); v.y = f2tf32f(v.y); v.z = f2tf32f(v.z); v.w = f2tf32f(v.w);
    ((float4*)dst)[i] = v;
}

// ---------------- embedding ----------------
__global__ void embed_kernel(const int* __restrict__ ids, const float* __restrict__ emb,
                             const float* __restrict__ pe, float* __restrict__ x,
                             float* __restrict__ xr) {
    int i  = blockIdx.x * blockDim.x + threadIdx.x;
    int d  = i % Dd;
    int bs = i / Dd;
    int s  = bs % Ss;
    float v = emb[(size_t)ids[bs] * Dd + d] + pe[(size_t)s * Dd + d];
    x[i]  = v;
    xr[i] = f2tf32f(v);
}

// ============ TF32 NT GEMM: C = A[M,K] @ B[N,K]^T (+bias, relu, round) ============
// Inputs pre-rounded to tf32 (mainloop is a pure bit copy).
// BM=128, BN=128, BK=32, 256 threads, warp tiles 64x32, 2 CTAs/SM.
// smem slot(k) = (k&3)*8 + (k>>2)  (rows stride 36) -> LDS.128 fragment loads.
template<bool BIAS, bool RELU, bool ROUND, bool SPLIT>
__global__ __launch_bounds__(256, 2) void gemm_tf32_nt(
    int M, int N, int K,
    const float* __restrict__ A, int lda,
    const float* __restrict__ B, int ldb,
    float* __restrict__ C, int ldc,
    const float* __restrict__ bias)
{
    __shared__ unsigned As[128 * 36];
    __shared__ unsigned Bs[128 * 36];

    const unsigned* Ap = (const unsigned*)(A + (size_t)(blockIdx.y * 128) * lda);
    const unsigned* Bp = (const unsigned*)(B + (size_t)(blockIdx.x * 128) * ldb);
    const int tid = threadIdx.x;
    const int lane = tid & 31, warp = tid >> 5;
    const int wm = (warp >> 2) * 64, wn = (warp & 3) * 32;
    const int grp = lane >> 2, tig = lane & 3;
    const int lrow = tid >> 3;            // 0..31
    const int lc4  = (tid & 7) * 4;       // 0..28

    uint4 ra[4], rb[4];
    float acc[4][4][4] = {};

    const int nk = K >> 5;
    for (int i = 0; i < nk; i++) {
        int k0 = i << 5;
        #pragma unroll
        for (int p = 0; p < 4; p++) {
            ra[p] = *(const uint4*)(Ap + (size_t)(lrow + p * 32) * lda + k0 + lc4);
            rb[p] = *(const uint4*)(Bp + (size_t)(lrow + p * 32) * ldb + k0 + lc4);
        }
        #pragma unroll
        for (int p = 0; p < 4; p++) {
            int base = (lrow + p * 32) * 36 + (lc4 >> 2);
            As[base + 0]  = ra[p].x; As[base + 8]  = ra[p].y;
            As[base + 16] = ra[p].z; As[base + 24] = ra[p].w;
            Bs[base + 0]  = rb[p].x; Bs[base + 8]  = rb[p].y;
            Bs[base + 16] = rb[p].z; Bs[base + 24] = rb[p].w;
        }
        __syncthreads();
        #pragma unroll
        for (int h = 0; h < 2; h++) {
            uint4 a0[4], a1[4];
            #pragma unroll
            for (int mi = 0; mi < 4; mi++) {
                int r = wm + mi * 16 + grp;
                a0[mi] = *(const uint4*)(As + r * 36 + tig * 8 + 4 * h);
                a1[mi] = *(const uint4*)(As + (r + 8) * 36 + tig * 8 + 4 * h);
            }
            #pragma unroll
            for (int ni = 0; ni < 4; ni++) {
                int nb = wn + ni * 8 + grp;
                uint4 bf = *(const uint4*)(Bs + nb * 36 + tig * 8 + 4 * h);
                #pragma unroll
                for (int mi = 0; mi < 4; mi++) {
                    mma_tf32(acc[mi][ni], a0[mi].x, a1[mi].x, a0[mi].y, a1[mi].y, bf.x, bf.y);
                    mma_tf32(acc[mi][ni], a0[mi].z, a1[mi].z, a0[mi].w, a1[mi].w, bf.z, bf.w);
                }
            }
        }
        __syncthreads();
    }

    #pragma unroll
    for (int mi = 0; mi < 4; mi++) {
        int row = blockIdx.y * 128 + wm + mi * 16 + grp;
        #pragma unroll
        for (int ni = 0; ni < 4; ni++) {
            int colg = blockIdx.x * 128 + wn + ni * 8 + 2 * tig;
            float* Cp;
            int col;
            if (SPLIT) {                         // route fused QKV output: n<768 -> Q, <1536 -> K, else V
                int qsel = blockIdx.x / 6;       // each 128-block lies wholly in one matrix
                Cp = C + (size_t)qsel * MOFF;
                col = colg - qsel * 768;
            } else {
                Cp = C;
                col = colg;
            }
            float b0 = 0.f, b1 = 0.f;
            if (BIAS) { b0 = bias[colg]; b1 = bias[colg + 1]; }
            float v0 = acc[mi][ni][0] + b0;
            float v1 = acc[mi][ni][1] + b1;
            float v2 = acc[mi][ni][2] + b0;
            float v3 = acc[mi][ni][3] + b1;
            if (RELU)  { v0 = fmaxf(v0, 0.f); v1 = fmaxf(v1, 0.f); v2 = fmaxf(v2, 0.f); v3 = fmaxf(v3, 0.f); }
            if (ROUND) { v0 = f2tf32f(v0); v1 = f2tf32f(v1); v2 = f2tf32f(v2); v3 = f2tf32f(v3); }
            *(float2*)(Cp + (size_t)row * ldc + col)       = make_float2(v0, v1);
            *(float2*)(Cp + (size_t)(row + 8) * ldc + col) = make_float2(v2, v3);
        }
    }
}

// ============ Flash attention: per (b,h), Q/K/V [1024,64] tf32-rounded ============
// Block = 256 threads (8 warps), Q tile 128 rows (warp owns 16), KV tiles of 64.
// smem words: Qs[2][128*36] Ks[2][64*36] Vs[2][64*36] Ps[2][128*36] = 110592 B
#define FL_SMEM (27648 * 4)
__global__ __launch_bounds__(256, 1) void flash_attn(
    const float* __restrict__ Qg, const float* __restrict__ Kg,
    const float* __restrict__ Vg, float* __restrict__ Og)
{
    extern __shared__ unsigned sm[];
    unsigned* Qs = sm;                      // [2][128*36]
    unsigned* Ks = sm + 2 * 128 * 36;       // [2][64*36]
    unsigned* Vs = Ks + 2 * 64 * 36;        // [2][64*36]
    unsigned* Ps = Vs + 2 * 64 * 36;        // [2][128*36]

    const int bh = blockIdx.y;
    const int qbase = blockIdx.x * 128;
    const unsigned* Qp = (const unsigned*)(Qg + (size_t)bh * Ss * HDh + (size_t)qbase * HDh);
    const unsigned* Kp = (const unsigned*)(Kg + (size_t)bh * Ss * HDh);
    const unsigned* Vp = (const unsigned*)(Vg + (size_t)bh * Ss * HDh);

    const int tid = threadIdx.x, lane = tid & 31, warp = tid >> 5;
    const int grp = lane >> 2, tig = lane & 3;
    const int wq = warp * 16;

    // ---- Q tile -> Qs (permuted) ----
    #pragma unroll
    for (int p = 0; p < 8; p++) {
        int i = tid + p * 256;        // 0..2047 float4s
        int row = i >> 4;
        int g16 = i & 15;
        int sub = g16 >> 3;
        int c4  = (g16 & 7) * 4;
        uint4 v = *(const uint4*)(Qp + (size_t)row * 64 + g16 * 4);
        unsigned* dst = Qs + sub * 128 * 36 + row * 36 + (c4 >> 2);
        dst[0] = v.x; dst[8] = v.y; dst[16] = v.z; dst[24] = v.w;
    }
    __syncthreads();

    // ---- Q fragments (held in regs for all 16 KV tiles) ----
    uint4 qf[2][2][2];
    #pragma unroll
    for (int s = 0; s < 2; s++) {
        const unsigned* q = Qs + s * 128 * 36;
        #pragma unroll
        for (int rh = 0; rh < 2; rh++) {
            int r = wq + grp + rh * 8;
            qf[s][rh][0] = *(const uint4*)(q + r * 36 + tig * 8);
            qf[s][rh][1] = *(const uint4*)(q + r * 36 + tig * 8 + 4);
        }
    }

    float oa[8][4];
    #pragma unroll
    for (int ni = 0; ni < 8; ni++) { oa[ni][0]=0.f; oa[ni][1]=0.f; oa[ni][2]=0.f; oa[ni][3]=0.f; }
    float m0 = -1e30f, m1 = -1e30f, l0 = 0.f, l1 = 0.f;

    for (int kv0 = 0; kv0 < Ss; kv0 += 64) {
        __syncthreads();
        // K tile (64x64) -> Ks (permuted)
        #pragma unroll
        for (int p = 0; p < 4; p++) {
            int i = tid + p * 256;    // 0..1023 float4s
            int row = i >> 4;
            int g16 = i & 15;
            int sub = g16 >> 3;
            int c4  = (g16 & 7) * 4;
            uint4 v = *(const uint4*)(Kp + (size_t)(kv0 + row) * 64 + g16 * 4);
            unsigned* dst = Ks + sub * 64 * 36 + row * 36 + (c4 >> 2);
            dst[0] = v.x; dst[8] = v.y; dst[16] = v.z; dst[24] = v.w;
        }
        // V tile (64 kv x 64 hd) -> Vs transposed ([n][k-slots], permuted)
        {
            int c = tid >> 6;         // k-class 0..3
            int n = tid & 63;
            #pragma unroll
            for (int s = 0; s < 2; s++) {
                unsigned vb[8];
                #pragma unroll
                for (int t = 0; t < 8; t++)
                    vb[t] = Vp[(size_t)(kv0 + s * 32 + c + 4 * t) * 64 + n];
                unsigned* dst = Vs + s * 64 * 36 + n * 36 + c * 8;
                *(uint4*)(dst)     = make_uint4(vb[0], vb[1], vb[2], vb[3]);
                *(uint4*)(dst + 4) = make_uint4(vb[4], vb[5], vb[6], vb[7]);
            }
        }
        __syncthreads();

        // ---- S = (Q K^T) / 8 ----
        float sacc[8][4];
        #pragma unroll
        for (int ni = 0; ni < 8; ni++) { sacc[ni][0]=0.f; sacc[ni][1]=0.f; sacc[ni][2]=0.f; sacc[ni][3]=0.f; }
        #pragma unroll
        for (int s = 0; s < 2; s++) {
            const unsigned* kb = Ks + s * 64 * 36;
            #pragma unroll
            for (int h = 0; h < 2; h++) {
                #pragma unroll
                for (int ni = 0; ni < 8; ni++) {
                    int nb = ni * 8 + grp;
                    uint4 bf = *(const uint4*)(kb + nb * 36 + tig * 8 + 4 * h);
                    mma_tf32(sacc[ni], qf[s][0][h].x, qf[s][1][h].x, qf[s][0][h].y, qf[s][1][h].y, bf.x, bf.y);
                    mma_tf32(sacc[ni], qf[s][0][h].z, qf[s][1][h].z, qf[s][0][h].w, qf[s][1][h].w, bf.z, bf.w);
                }
            }
        }

        // ---- online softmax ----
        float mx0 = -1e30f, mx1 = -1e30f;
        #pragma unroll
        for (int ni = 0; ni < 8; ni++) {
            sacc[ni][0] *= 0.125f; sacc[ni][1] *= 0.125f; sacc[ni][2] *= 0.125f; sacc[ni][3] *= 0.125f;
            mx0 = fmaxf(mx0, fmaxf(sacc[ni][0], sacc[ni][1]));
            mx1 = fmaxf(mx1, fmaxf(sacc[ni][2], sacc[ni][3]));
        }
        mx0 = fmaxf(mx0, __shfl_xor_sync(0xffffffffu, mx0, 1));
        mx0 = fmaxf(mx0, __shfl_xor_sync(0xffffffffu, mx0, 2));
        mx1 = fmaxf(mx1, __shfl_xor_sync(0xffffffffu, mx1, 1));
        mx1 = fmaxf(mx1, __shfl_xor_sync(0xffffffffu, mx1, 2));
        float mn0 = fmaxf(m0, mx0), mn1 = fmaxf(m1, mx1);
        float al0 = __expf(m0 - mn0), al1 = __expf(m1 - mn1);
        float sum0 = 0.f, sum1 = 0.f;
        {
            int r0 = wq + grp, r1 = r0 + 8;
            #pragma unroll
            for (int ni = 0; ni < 8; ni++) {
                float p0 = __expf(sacc[ni][0] - mn0);
                float p1 = __expf(sacc[ni][1] - mn0);
                float p2 = __expf(sacc[ni][2] - mn1);
                float p3 = __expf(sacc[ni][3] - mn1);
                sum0 += p0 + p1; sum1 += p2 + p3;
                int j  = ni * 8 + 2 * tig;
                int sub = j >> 5, jj = j & 31;
                unsigned* pp = Ps + sub * 128 * 36;
                int s0 = (jj & 3) * 8 + (jj >> 2);
                int s1 = ((jj + 1) & 3) * 8 + ((jj + 1) >> 2);
                pp[r0 * 36 + s0] = f2tf32u(p0);
                pp[r0 * 36 + s1] = f2tf32u(p1);
                pp[r1 * 36 + s0] = f2tf32u(p2);
                pp[r1 * 36 + s1] = f2tf32u(p3);
            }
        }
        sum0 += __shfl_xor_sync(0xffffffffu, sum0, 1);
        sum0 += __shfl_xor_sync(0xffffffffu, sum0, 2);
        sum1 += __shfl_xor_sync(0xffffffffu, sum1, 1);
        sum1 += __shfl_xor_sync(0xffffffffu, sum1, 2);
        l0 = l0 * al0 + sum0;  l1 = l1 * al1 + sum1;
        m0 = mn0;  m1 = mn1;
        #pragma unroll
        for (int ni = 0; ni < 8; ni++) {
            oa[ni][0] *= al0; oa[ni][1] *= al0; oa[ni][2] *= al1; oa[ni][3] *= al1;
        }
        __syncwarp();

        // ---- O += P V ----
        uint4 pf[2][2][2];
        #pragma unroll
        for (int s = 0; s < 2; s++) {
            const unsigned* p = Ps + s * 128 * 36;
            #pragma unroll
            for (int rh = 0; rh < 2; rh++) {
                int r = wq + grp + rh * 8;
                pf[s][rh][0] = *(const uint4*)(p + r * 36 + tig * 8);
                pf[s][rh][1] = *(const uint4*)(p + r * 36 + tig * 8 + 4);
            }
        }
        #pragma unroll
        for (int s = 0; s < 2; s++) {
            const unsigned* vbp = Vs + s * 64 * 36;
            #pragma unroll
            for (int h = 0; h < 2; h++) {
                #pragma unroll
                for (int ni = 0; ni < 8; ni++) {
                    int nb = ni * 8 + grp;
                    uint4 bf = *(const uint4*)(vbp + nb * 36 + tig * 8 + 4 * h);
                    mma_tf32(oa[ni], pf[s][0][h].x, pf[s][1][h].x, pf[s][0][h].y, pf[s][1][h].y, bf.x, bf.y);
                    mma_tf32(oa[ni], pf[s][0][h].z, pf[s][1][h].z, pf[s][0][h].w, pf[s][1][h].w, bf.z, bf.w);
                }
            }
        }
    }

    // ---- epilogue ----
    float i0 = 1.f / l0, i1 = 1.f / l1;
    const int b = bh / Hh, h = bh % Hh;
    float* Op = Og + (size_t)b * Ss * Dd + (size_t)qbase * Dd + h * HDh;
    int r0 = wq + grp;
    #pragma unroll
    for (int ni = 0; ni < 8; ni++) {
        int col = ni * 8 + 2 * tig;
        *(float2*)(Op + (size_t)r0 * Dd + col)       = make_float2(oa[ni][0] * i0, oa[ni][1] * i0);
        *(float2*)(Op + (size_t)(r0 + 8) * Dd + col) = make_float2(oa[ni][2] * i1, oa[ni][3] * i1);
    }
}

// ---------------- add + layernorm (+ optional rounded copy) ----------------
__global__ __launch_bounds__(256) void add_ln_kernel(
    const float* __restrict__ x, const float* __restrict__ h,
    const float* __restrict__ g, const float* __restrict__ bias,
    float* __restrict__ out, float* __restrict__ outr)
{
    const size_t row = blockIdx.x;
    const float* px = x + row * Dd;
    const float* ph = h + row * Dd;
    int t = threadIdx.x;
    float v[3];
    #pragma unroll
    for (int i = 0; i < 3; i++) v[i] = px[t + i * 256] + ph[t + i * 256];
    float mu = blockReduceSum(v[0] + v[1] + v[2]) * (1.f / Dd);
    float q = 0.f;
    #pragma unroll
    for (int i = 0; i < 3; i++) { float d = v[i] - mu; q += d * d; }
    float var = blockReduceSum(q) * (1.f / Dd);
    float inv = rsqrtf(var + 1e-5f);
    float* po = out + row * Dd;
    float* pr = outr ? outr + row * Dd : nullptr;
    #pragma unroll
    for (int i = 0; i < 3; i++) {
        int c = t + i * 256;
        float o = (v[i] - mu) * inv * g[c] + bias[c];
        po[c] = o;
        if (pr) pr[c] = f2tf32f(o);
    }
}

// ---------------- host launcher ----------------
extern "C" void kernel_launch(void* const* d_in, const int* in_sizes, int n_in,
                              void* d_out, int out_size) {
    const int*   ids  = (const int*)  d_in[0];
    const float* emb  = (const float*)d_in[1];
    const float* pe   = (const float*)d_in[2];
    const float* Wq   = (const float*)d_in[3];
    const float* bq   = (const float*)d_in[4];
    const float* Wk   = (const float*)d_in[5];
    const float* bk   = (const float*)d_in[6];
    const float* Wv   = (const float*)d_in[7];
    const float* bv   = (const float*)d_in[8];
    const float* W1   = (const float*)d_in[9];
    const float* b1   = (const float*)d_in[10];
    const float* W2   = (const float*)d_in[11];
    const float* b2   = (const float*)d_in[12];
    const float* ln1g = (const float*)d_in[13];
    const float* ln1b = (const float*)d_in[14];
    const float* ln2g = (const float*)d_in[15];
    const float* ln2b = (const float*)d_in[16];

    float *X, *Xr, *QKV, *Hb, *Y1, *Y1r, *F, *Wqkv, *Bqkv, *W1r, *W2r;
    cudaGetSymbolAddress((void**)&X,    gX);
    cudaGetSymbolAddress((void**)&Xr,   gXr);
    cudaGetSymbolAddress((void**)&QKV,  gQKV);
    cudaGetSymbolAddress((void**)&Hb,   gHb);
    cudaGetSymbolAddress((void**)&Y1,   gY1);
    cudaGetSymbolAddress((void**)&Y1r,  gY1r);
    cudaGetSymbolAddress((void**)&F,    gF);
    cudaGetSymbolAddress((void**)&Wqkv, gWqkv);
    cudaGetSymbolAddress((void**)&Bqkv, gBqkv);
    cudaGetSymbolAddress((void**)&W1r,  gW1r);
    cudaGetSymbolAddress((void**)&W2r,  gW2r);

    cudaFuncSetAttribute(flash_attn, cudaFuncAttributeMaxDynamicSharedMemorySize, FL_SMEM);

    const int M = Bb * Ss;   // 8192

    // weight prep (pure memory passes, ~50us total)
    pack_qkv_w<<<(LL * 2304 * 192) / 256, 256>>>(Wqkv, Wq, Wk, Wv);
    pack_qkv_b<<<(LL * 2304) / 256, 256>>>(Bqkv, bq, bk, bv);
    round_kernel<<<(LL * DFF * Dd) / 1024, 256>>>(W1r, W1);
    round_kernel<<<(LL * Dd * DFF) / 1024, 256>>>(W2r, W2);

    embed_kernel<<<(Bb * Ss * Dd) / 256, 256>>>(ids, emb, pe, X, Xr);

    for (int l = 0; l < LL; l++) {
        // fused QKV projection (rounded outputs, routed to Q/K/V)
        gemm_tf32_nt<true, false, true, true><<<dim3(18, M / 128), 256>>>(
            M, 3 * Dd, Dd, Xr, Dd, Wqkv + (size_t)l * 3 * Dd * Dd, Dd,
            QKV, Dd, Bqkv + (size_t)l * 3 * Dd);

        // fused attention (scores + softmax + AV)
        flash_attn<<<dim3(Ss / 128, Bb * Hh), 256, FL_SMEM>>>(
            QKV, QKV + MOFF, QKV + 2 * MOFF, Hb);

        add_ln_kernel<<<M, 256>>>(X, Hb, ln1g + l * Dd, ln1b + l * Dd, Y1, Y1r);

        gemm_tf32_nt<true, true, true, false><<<dim3(DFF / 128, M / 128), 256>>>(
            M, DFF, Dd, Y1r, Dd, W1r + (size_t)l * DFF * Dd, Dd, F, DFF, b1 + l * DFF);
        gemm_tf32_nt<true, false, false, false><<<dim3(Dd / 128, M / 128), 256>>>(
            M, Dd, DFF, F, DFF, W2r + (size_t)l * Dd * DFF, DFF, Hb, Dd, b2 + l * Dd);

        float* outp = (l == LL - 1) ? (float*)d_out : X;
        float* outr = (l == LL - 1) ? nullptr : Xr;
        add_ln_kernel<<<M, 256>>>(Y1, Hb, ln2g + l * Dd, ln2b + l * Dd, outp, outr);
    }
}

// round 7
// speedup vs baseline: 1.5616x; 1.1305x over previous
#include <cuda_runtime.h>
#include <math.h>

#define Bb   8
#define Ss   1024
#define Dd   768
#define Hh   12
#define HDh  64
#define DFF  3072
#define LL   6
#define MOFF (Bb*Ss*Dd)      // 6291456, size of one of Q/K/V

// ---------------- scratch (all activation/weight tensors in "P-layout":
// within each 32-aligned feature block, logical k stored at (k&3)*8 + (k>>2)) --------
__device__ float gX   [Bb*Ss*Dd];
__device__ float gXr  [Bb*Ss*Dd];
__device__ float gQKV [3*Bb*Ss*Dd];
__device__ float gHb  [Bb*Ss*Dd];
__device__ float gY1  [Bb*Ss*Dd];
__device__ float gY1r [Bb*Ss*Dd];
__device__ float gF   [Bb*Ss*DFF];
__device__ float gWqkv[LL*3*Dd*Dd];
__device__ float gBqkv[LL*3*Dd];
__device__ float gW1r [LL*DFF*Dd];
__device__ float gW2r [LL*Dd*DFF];
__device__ float gB1p [LL*DFF];
__device__ float gB2p [LL*Dd];
__device__ float gLn1g[LL*Dd];
__device__ float gLn1b[LL*Dd];
__device__ float gLn2g[LL*Dd];
__device__ float gLn2b[LL*Dd];

// ---------------- helpers ----------------
__device__ __forceinline__ int inv32(int j) { return ((j & 7) << 2) | (j >> 3); }

__device__ __forceinline__ float f2tf32f(float f) {
    unsigned u;
    asm("cvt.rna.tf32.f32 %0, %1;" : "=r"(u) : "f"(f));
    return __uint_as_float(u);
}
__device__ __forceinline__ unsigned f2tf32u(float f) {
    unsigned u;
    asm("cvt.rna.tf32.f32 %0, %1;" : "=r"(u) : "f"(f));
    return u;
}

__device__ __forceinline__ void mma_tf32(float c[4], unsigned a0, unsigned a1, unsigned a2, unsigned a3,
                                         unsigned b0, unsigned b1) {
    asm volatile(
        "mma.sync.aligned.m16n8k8.row.col.f32.tf32.tf32.f32 "
        "{%0,%1,%2,%3}, {%4,%5,%6,%7}, {%8,%9}, {%0,%1,%2,%3};\n"
        : "+f"(c[0]), "+f"(c[1]), "+f"(c[2]), "+f"(c[3])
        : "r"(a0), "r"(a1), "r"(a2), "r"(a3), "r"(b0), "r"(b1));
}

__device__ __forceinline__ void cp16(unsigned* smem_dst, const void* gmem_src) {
    unsigned s = (unsigned)__cvta_generic_to_shared(smem_dst);
    asm volatile("cp.async.cg.shared.global [%0], [%1], 16;\n" :: "r"(s), "l"(gmem_src));
}
#define CP_COMMIT asm volatile("cp.async.commit_group;\n" ::)
#define CP_WAIT1  asm volatile("cp.async.wait_group 1;\n" ::)
#define CP_WAIT0  asm volatile("cp.async.wait_group 0;\n" ::)

__device__ __forceinline__ float blockReduceSum(float v) {
    __shared__ float red[32];
    #pragma unroll
    for (int o = 16; o > 0; o >>= 1) v += __shfl_xor_sync(0xffffffffu, v, o);
    int lane = threadIdx.x & 31, w = threadIdx.x >> 5;
    if (lane == 0) red[w] = v;
    __syncthreads();
    v = (threadIdx.x < 8) ? red[threadIdx.x] : 0.f;
    if (w == 0) {
        #pragma unroll
        for (int o = 4; o > 0; o >>= 1) v += __shfl_xor_sync(0xffffffffu, v, o);
        if (lane == 0) red[0] = v;
    }
    __syncthreads();
    float r = red[0];
    __syncthreads();
    return r;
}

// ---------------- prep: permute+round weights, permute params ----------------
// dst phys (rp, cp); gathers logical (inv(rp), inv(cp)).
__global__ void perm_weight(float* __restrict__ dst, const float* __restrict__ src,
                            int rowsPerL, int cols, long dstL, long srcL) {
    long i = (long)blockIdx.x * blockDim.x + threadIdx.x;
    long per = (long)rowsPerL * cols;
    int l = (int)(i / per);
    long rem = i % per;
    int rp = (int)(rem / cols), cp = (int)(rem % cols);
    int r = (rp & ~31) | inv32(rp & 31);
    int c = (cp & ~31) | inv32(cp & 31);
    dst[l * dstL + (long)rp * cols + cp] = f2tf32f(src[l * srcL + (long)r * cols + c]);
}

__global__ void perm_vec(float* __restrict__ dst, const float* __restrict__ src) {
    int i = blockIdx.x * blockDim.x + threadIdx.x;
    dst[i] = src[(i & ~31) | inv32(i & 31)];
}

__global__ void pack_qkv_b(float* __restrict__ dst, const float* __restrict__ bq,
                           const float* __restrict__ bk, const float* __restrict__ bv) {
    int i = blockIdx.x * blockDim.x + threadIdx.x;     // phys over LL*2304
    int pos = (i & ~31) | inv32(i & 31);
    int l = pos / 2304, n = pos % 2304;
    dst[i] = (n < 768) ? bq[l * 768 + n] : (n < 1536) ? bk[l * 768 + n - 768] : bv[l * 768 + n - 1536];
}

// ---------------- embedding (writes P-layout) ----------------
__global__ void embed_kernel(const int* __restrict__ ids, const float* __restrict__ emb,
                             const float* __restrict__ pe, float* __restrict__ x,
                             float* __restrict__ xr) {
    int i  = blockIdx.x * blockDim.x + threadIdx.x;
    int dp = i % Dd;
    int bs = i / Dd;
    int s  = bs % Ss;
    int d  = (dp & ~31) | inv32(dp & 31);
    float v = emb[(size_t)ids[bs] * Dd + d] + pe[(size_t)s * Dd + d];
    x[i]  = v;
    xr[i] = f2tf32f(v);
}

// ============ TF32 NT GEMM, cp.async double-buffered ============
// All operands in P-layout, pre-rounded. BM=128, BN=128, BK=32, 256 thr, 2 CTA/SM.
// Stage = 9216 words: As[128*36] + Bs[128*36]. smem slot j within tile = phys word j.
template<bool BIAS, bool RELU, bool ROUND, bool SPLIT>
__global__ __launch_bounds__(256, 2) void gemm_tf32_nt(
    int M, int N, int K,
    const float* __restrict__ A, int lda,
    const float* __restrict__ B, int ldb,
    float* __restrict__ C, int ldc,
    const float* __restrict__ bias)
{
    extern __shared__ unsigned sm[];
    const unsigned* Ap = (const unsigned*)(A + (size_t)(blockIdx.y * 128) * lda);
    const unsigned* Bp = (const unsigned*)(B + (size_t)(blockIdx.x * 128) * ldb);
    const int tid = threadIdx.x;
    const int lane = tid & 31, warp = tid >> 5;
    const int wm = (warp >> 2) * 64, wn = (warp & 3) * 32;
    const int grp = lane >> 2, tig = lane & 3;
    const int lrow = tid >> 3;            // 0..31
    const int lc4  = (tid & 7) * 4;       // 0..28

    float acc[4][4][4] = {};
    const int nk = K >> 5;

    auto ISSUE = [&](int i) {
        int k0 = i << 5;
        unsigned* base = sm + (i & 1) * 9216;
        #pragma unroll
        for (int p = 0; p < 4; p++) {
            int r = lrow + p * 32;
            cp16(base + r * 36 + lc4,        Ap + (size_t)r * lda + k0 + lc4);
            cp16(base + 4608 + r * 36 + lc4, Bp + (size_t)r * ldb + k0 + lc4);
        }
        CP_COMMIT;
    };

    ISSUE(0);
    for (int i = 0; i < nk; i++) {
        if (i + 1 < nk) { ISSUE(i + 1); CP_WAIT1; }
        else            { CP_WAIT0; }
        __syncthreads();
        const unsigned* As = sm + (i & 1) * 9216;
        const unsigned* Bs = As + 4608;
        #pragma unroll
        for (int h = 0; h < 2; h++) {
            uint4 a0[4], a1[4];
            #pragma unroll
            for (int mi = 0; mi < 4; mi++) {
                int r = wm + mi * 16 + grp;
                a0[mi] = *(const uint4*)(As + r * 36 + tig * 8 + 4 * h);
                a1[mi] = *(const uint4*)(As + (r + 8) * 36 + tig * 8 + 4 * h);
            }
            #pragma unroll
            for (int ni = 0; ni < 4; ni++) {
                int nb = wn + ni * 8 + grp;
                uint4 bf = *(const uint4*)(Bs + nb * 36 + tig * 8 + 4 * h);
                #pragma unroll
                for (int mi = 0; mi < 4; mi++) {
                    mma_tf32(acc[mi][ni], a0[mi].x, a1[mi].x, a0[mi].y, a1[mi].y, bf.x, bf.y);
                    mma_tf32(acc[mi][ni], a0[mi].z, a1[mi].z, a0[mi].w, a1[mi].w, bf.z, bf.w);
                }
            }
        }
        __syncthreads();
    }

    #pragma unroll
    for (int mi = 0; mi < 4; mi++) {
        int row = blockIdx.y * 128 + wm + mi * 16 + grp;
        #pragma unroll
        for (int ni = 0; ni < 4; ni++) {
            int colg = blockIdx.x * 128 + wn + ni * 8 + 2 * tig;   // phys col
            float* Cp;
            int col;
            if (SPLIT) {
                int qsel = blockIdx.x / 6;
                Cp = C + (size_t)qsel * MOFF;
                col = colg - qsel * 768;
            } else {
                Cp = C;
                col = colg;
            }
            float b0 = 0.f, b1 = 0.f;
            if (BIAS) { b0 = bias[colg]; b1 = bias[colg + 1]; }
            float v0 = acc[mi][ni][0] + b0;
            float v1 = acc[mi][ni][1] + b1;
            float v2 = acc[mi][ni][2] + b0;
            float v3 = acc[mi][ni][3] + b1;
            if (RELU)  { v0 = fmaxf(v0, 0.f); v1 = fmaxf(v1, 0.f); v2 = fmaxf(v2, 0.f); v3 = fmaxf(v3, 0.f); }
            if (ROUND) { v0 = f2tf32f(v0); v1 = f2tf32f(v1); v2 = f2tf32f(v2); v3 = f2tf32f(v3); }
            *(float2*)(Cp + (size_t)row * ldc + col)       = make_float2(v0, v1);
            *(float2*)(Cp + (size_t)(row + 8) * ldc + col) = make_float2(v2, v3);
        }
    }
}

// ============ Flash attention (Q/K/V in P-layout along head-dim) ============
#define FL_SMEM (27648 * 4)
__global__ __launch_bounds__(256, 1) void flash_attn(
    const float* __restrict__ Qg, const float* __restrict__ Kg,
    const float* __restrict__ Vg, float* __restrict__ Og)
{
    extern __shared__ unsigned sm[];
    unsigned* Qs = sm;                      // [2][128*36]
    unsigned* Ks = sm + 2 * 128 * 36;       // [2][64*36]
    unsigned* Vs = Ks + 2 * 64 * 36;        // [2][64*36]
    unsigned* Ps = Vs + 2 * 64 * 36;        // [2][128*36]

    const int bh = blockIdx.y;
    const int qbase = blockIdx.x * 128;
    const unsigned* Qp = (const unsigned*)(Qg + (size_t)bh * Ss * HDh + (size_t)qbase * HDh);
    const unsigned* Kp = (const unsigned*)(Kg + (size_t)bh * Ss * HDh);
    const unsigned* Vp = (const unsigned*)(Vg + (size_t)bh * Ss * HDh);

    const int tid = threadIdx.x, lane = tid & 31, warp = tid >> 5;
    const int grp = lane >> 2, tig = lane & 3;
    const int wq = warp * 16;

    // Q tile -> Qs (verbatim: global already permuted)
    #pragma unroll
    for (int p = 0; p < 8; p++) {
        int i = tid + p * 256;
        int row = i >> 4, f = i & 15;
        uint4 v = *(const uint4*)(Qp + (size_t)row * 64 + f * 4);
        *(uint4*)(Qs + (f >> 3) * 128 * 36 + row * 36 + (f & 7) * 4) = v;
    }
    __syncthreads();

    uint4 qf[2][2][2];
    #pragma unroll
    for (int s = 0; s < 2; s++) {
        const unsigned* q = Qs + s * 128 * 36;
        #pragma unroll
        for (int rh = 0; rh < 2; rh++) {
            int r = wq + grp + rh * 8;
            qf[s][rh][0] = *(const uint4*)(q + r * 36 + tig * 8);
            qf[s][rh][1] = *(const uint4*)(q + r * 36 + tig * 8 + 4);
        }
    }

    float oa[8][4];
    #pragma unroll
    for (int ni = 0; ni < 8; ni++) { oa[ni][0]=0.f; oa[ni][1]=0.f; oa[ni][2]=0.f; oa[ni][3]=0.f; }
    float m0 = -1e30f, m1 = -1e30f, l0 = 0.f, l1 = 0.f;

    for (int kv0 = 0; kv0 < Ss; kv0 += 64) {
        __syncthreads();
        #pragma unroll
        for (int p = 0; p < 4; p++) {
            int i = tid + p * 256;
            int row = i >> 4, f = i & 15;
            uint4 v = *(const uint4*)(Kp + (size_t)(kv0 + row) * 64 + f * 4);
            *(uint4*)(Ks + (f >> 3) * 64 * 36 + row * 36 + (f & 7) * 4) = v;
        }
        {
            int c = tid >> 6;
            int n = tid & 63;                 // phys head-dim column
            #pragma unroll
            for (int s = 0; s < 2; s++) {
                unsigned vb[8];
                #pragma unroll
                for (int t = 0; t < 8; t++)
                    vb[t] = Vp[(size_t)(kv0 + s * 32 + c + 4 * t) * 64 + n];
                unsigned* dst = Vs + s * 64 * 36 + n * 36 + c * 8;
                *(uint4*)(dst)     = make_uint4(vb[0], vb[1], vb[2], vb[3]);
                *(uint4*)(dst + 4) = make_uint4(vb[4], vb[5], vb[6], vb[7]);
            }
        }
        __syncthreads();

        float sacc[8][4];
        #pragma unroll
        for (int ni = 0; ni < 8; ni++) { sacc[ni][0]=0.f; sacc[ni][1]=0.f; sacc[ni][2]=0.f; sacc[ni][3]=0.f; }
        #pragma unroll
        for (int s = 0; s < 2; s++) {
            const unsigned* kb = Ks + s * 64 * 36;
            #pragma unroll
            for (int h = 0; h < 2; h++) {
                #pragma unroll
                for (int ni = 0; ni < 8; ni++) {
                    int nb = ni * 8 + grp;
                    uint4 bf = *(const uint4*)(kb + nb * 36 + tig * 8 + 4 * h);
                    mma_tf32(sacc[ni], qf[s][0][h].x, qf[s][1][h].x, qf[s][0][h].y, qf[s][1][h].y, bf.x, bf.y);
                    mma_tf32(sacc[ni], qf[s][0][h].z, qf[s][1][h].z, qf[s][0][h].w, qf[s][1][h].w, bf.z, bf.w);
                }
            }
        }

        float mx0 = -1e30f, mx1 = -1e30f;
        #pragma unroll
        for (int ni = 0; ni < 8; ni++) {
            sacc[ni][0] *= 0.125f; sacc[ni][1] *= 0.125f; sacc[ni][2] *= 0.125f; sacc[ni][3] *= 0.125f;
            mx0 = fmaxf(mx0, fmaxf(sacc[ni][0], sacc[ni][1]));
            mx1 = fmaxf(mx1, fmaxf(sacc[ni][2], sacc[ni][3]));
        }
        mx0 = fmaxf(mx0, __shfl_xor_sync(0xffffffffu, mx0, 1));
        mx0 = fmaxf(mx0, __shfl_xor_sync(0xffffffffu, mx0, 2));
        mx1 = fmaxf(mx1, __shfl_xor_sync(0xffffffffu, mx1, 1));
        mx1 = fmaxf(mx1, __shfl_xor_sync(0xffffffffu, mx1, 2));
        float mn0 = fmaxf(m0, mx0), mn1 = fmaxf(m1, mx1);
        float al0 = __expf(m0 - mn0), al1 = __expf(m1 - mn1);
        float sum0 = 0.f, sum1 = 0.f;
        {
            int r0 = wq + grp, r1 = r0 + 8;
            #pragma unroll
            for (int ni = 0; ni < 8; ni++) {
                float p0 = __expf(sacc[ni][0] - mn0);
                float p1 = __expf(sacc[ni][1] - mn0);
                float p2 = __expf(sacc[ni][2] - mn1);
                float p3 = __expf(sacc[ni][3] - mn1);
                sum0 += p0 + p1; sum1 += p2 + p3;
                int j  = ni * 8 + 2 * tig;
                int sub = j >> 5, jj = j & 31;
                unsigned* pp = Ps + sub * 128 * 36;
                int s0 = (jj & 3) * 8 + (jj >> 2);
                int s1 = ((jj + 1) & 3) * 8 + ((jj + 1) >> 2);
                pp[r0 * 36 + s0] = f2tf32u(p0);
                pp[r0 * 36 + s1] = f2tf32u(p1);
                pp[r1 * 36 + s0] = f2tf32u(p2);
                pp[r1 * 36 + s1] = f2tf32u(p3);
            }
        }
        sum0 += __shfl_xor_sync(0xffffffffu, sum0, 1);
        sum0 += __shfl_xor_sync(0xffffffffu, sum0, 2);
        sum1 += __shfl_xor_sync(0xffffffffu, sum1, 1);
        sum1 += __shfl_xor_sync(0xffffffffu, sum1, 2);
        l0 = l0 * al0 + sum0;  l1 = l1 * al1 + sum1;
        m0 = mn0;  m1 = mn1;
        #pragma unroll
        for (int ni = 0; ni < 8; ni++) {
            oa[ni][0] *= al0; oa[ni][1] *= al0; oa[ni][2] *= al1; oa[ni][3] *= al1;
        }
        __syncwarp();

        uint4 pf[2][2][2];
        #pragma unroll
        for (int s = 0; s < 2; s++) {
            const unsigned* p = Ps + s * 128 * 36;
            #pragma unroll
            for (int rh = 0; rh < 2; rh++) {
                int r = wq + grp + rh * 8;
                pf[s][rh][0] = *(const uint4*)(p + r * 36 + tig * 8);
                pf[s][rh][1] = *(const uint4*)(p + r * 36 + tig * 8 + 4);
            }
        }
        #pragma unroll
        for (int s = 0; s < 2; s++) {
            const unsigned* vbp = Vs + s * 64 * 36;
            #pragma unroll
            for (int h = 0; h < 2; h++) {
                #pragma unroll
                for (int ni = 0; ni < 8; ni++) {
                    int nb = ni * 8 + grp;
                    uint4 bf = *(const uint4*)(vbp + nb * 36 + tig * 8 + 4 * h);
                    mma_tf32(oa[ni], pf[s][0][h].x, pf[s][1][h].x, pf[s][0][h].y, pf[s][1][h].y, bf.x, bf.y);
                    mma_tf32(oa[ni], pf[s][0][h].z, pf[s][1][h].z, pf[s][0][h].w, pf[s][1][h].w, bf.z, bf.w);
                }
            }
        }
    }

    float i0 = 1.f / l0, i1 = 1.f / l1;
    const int b = bh / Hh, h = bh % Hh;
    float* Op = Og + (size_t)b * Ss * Dd + (size_t)qbase * Dd + h * HDh;
    int r0 = wq + grp;
    #pragma unroll
    for (int ni = 0; ni < 8; ni++) {
        int col = ni * 8 + 2 * tig;          // phys head-dim
        *(float2*)(Op + (size_t)r0 * Dd + col)       = make_float2(oa[ni][0] * i0, oa[ni][1] * i0);
        *(float2*)(Op + (size_t)(r0 + 8) * Dd + col) = make_float2(oa[ni][2] * i1, oa[ni][3] * i1);
    }
}

// ---------------- add + layernorm (P-layout; optional final unpermute) ----------------
__global__ __launch_bounds__(256) void add_ln_kernel(
    const float* __restrict__ x, const float* __restrict__ h,
    const float* __restrict__ g, const float* __restrict__ bias,
    float* __restrict__ out, float* __restrict__ outr, int unperm)
{
    const size_t row = blockIdx.x;
    const float* px = x + row * Dd;
    const float* ph = h + row * Dd;
    int t = threadIdx.x;
    float v[3];
    #pragma unroll
    for (int i = 0; i < 3; i++) v[i] = px[t + i * 256] + ph[t + i * 256];
    float mu = blockReduceSum(v[0] + v[1] + v[2]) * (1.f / Dd);
    float q = 0.f;
    #pragma unroll
    for (int i = 0; i < 3; i++) { float d = v[i] - mu; q += d * d; }
    float var = blockReduceSum(q) * (1.f / Dd);
    float inv = rsqrtf(var + 1e-5f);
    float* po = out + row * Dd;
    float* pr = outr ? outr + row * Dd : nullptr;
    #pragma unroll
    for (int i = 0; i < 3; i++) {
        int c = t + i * 256;
        float o = (v[i] - mu) * inv * g[c] + bias[c];
        int dstc = unperm ? ((c & ~31) | inv32(c & 31)) : c;
        po[dstc] = o;
        if (pr) pr[c] = f2tf32f(o);
    }
}

// ---------------- host launcher ----------------
extern "C" void kernel_launch(void* const* d_in, const int* in_sizes, int n_in,
                              void* d_out, int out_size) {
    const int*   ids  = (const int*)  d_in[0];
    const float* emb  = (const float*)d_in[1];
    const float* pe   = (const float*)d_in[2];
    const float* Wq   = (const float*)d_in[3];
    const float* bq   = (const float*)d_in[4];
    const float* Wk   = (const float*)d_in[5];
    const float* bk   = (const float*)d_in[6];
    const float* Wv   = (const float*)d_in[7];
    const float* bv   = (const float*)d_in[8];
    const float* W1   = (const float*)d_in[9];
    const float* b1   = (const float*)d_in[10];
    const float* W2   = (const float*)d_in[11];
    const float* b2   = (const float*)d_in[12];
    const float* ln1g = (const float*)d_in[13];
    const float* ln1b = (const float*)d_in[14];
    const float* ln2g = (const float*)d_in[15];
    const float* ln2b = (const float*)d_in[16];

    float *X, *Xr, *QKV, *Hb, *Y1, *Y1r, *F, *Wqkv, *Bqkv, *W1r, *W2r;
    float *B1p, *B2p, *L1g, *L1b, *L2g, *L2b;
    cudaGetSymbolAddress((void**)&X,    gX);
    cudaGetSymbolAddress((void**)&Xr,   gXr);
    cudaGetSymbolAddress((void**)&QKV,  gQKV);
    cudaGetSymbolAddress((void**)&Hb,   gHb);
    cudaGetSymbolAddress((void**)&Y1,   gY1);
    cudaGetSymbolAddress((void**)&Y1r,  gY1r);
    cudaGetSymbolAddress((void**)&F,    gF);
    cudaGetSymbolAddress((void**)&Wqkv, gWqkv);
    cudaGetSymbolAddress((void**)&Bqkv, gBqkv);
    cudaGetSymbolAddress((void**)&W1r,  gW1r);
    cudaGetSymbolAddress((void**)&W2r,  gW2r);
    cudaGetSymbolAddress((void**)&B1p,  gB1p);
    cudaGetSymbolAddress((void**)&B2p,  gB2p);
    cudaGetSymbolAddress((void**)&L1g,  gLn1g);
    cudaGetSymbolAddress((void**)&L1b,  gLn1b);
    cudaGetSymbolAddress((void**)&L2g,  gLn2g);
    cudaGetSymbolAddress((void**)&L2b,  gLn2b);

    const int NT_SMEM = 2 * 9216 * 4;   // 73728 B
    cudaFuncSetAttribute(gemm_tf32_nt<true,  false, true,  true >, cudaFuncAttributeMaxDynamicSharedMemorySize, NT_SMEM);
    cudaFuncSetAttribute(gemm_tf32_nt<true,  true,  true,  false>, cudaFuncAttributeMaxDynamicSharedMemorySize, NT_SMEM);
    cudaFuncSetAttribute(gemm_tf32_nt<true,  false, false, false>, cudaFuncAttributeMaxDynamicSharedMemorySize, NT_SMEM);
    cudaFuncSetAttribute(flash_attn, cudaFuncAttributeMaxDynamicSharedMemorySize, FL_SMEM);

    const int M = Bb * Ss;   // 8192

    // prep: permute+round weights, permute biases/params (memory-bound, ~40us)
    perm_weight<<<(LL * 768 * 768)  / 256, 256>>>(Wqkv,             Wq, 768,  768, 2304L*768, 768L*768);
    perm_weight<<<(LL * 768 * 768)  / 256, 256>>>(Wqkv + 768*768,   Wk, 768,  768, 2304L*768, 768L*768);
    perm_weight<<<(LL * 768 * 768)  / 256, 256>>>(Wqkv + 1536*768,  Wv, 768,  768, 2304L*768, 768L*768);
    perm_weight<<<(LL * DFF * 768)  / 256, 256>>>(W1r,              W1, DFF,  768, (long)DFF*768, (long)DFF*768);
    perm_weight<<<(LL * 768 * DFF)  / 256, 256>>>(W2r,              W2, 768,  DFF, 768L*DFF, 768L*DFF);
    pack_qkv_b<<<(LL * 2304) / 256, 256>>>(Bqkv, bq, bk, bv);
    perm_vec<<<(LL * DFF) / 256, 256>>>(B1p, b1);
    perm_vec<<<(LL * Dd)  / 256, 256>>>(B2p, b2);
    perm_vec<<<(LL * Dd)  / 256, 256>>>(L1g, ln1g);
    perm_vec<<<(LL * Dd)  / 256, 256>>>(L1b, ln1b);
    perm_vec<<<(LL * Dd)  / 256, 256>>>(L2g, ln2g);
    perm_vec<<<(LL * Dd)  / 256, 256>>>(L2b, ln2b);

    embed_kernel<<<(Bb * Ss * Dd) / 256, 256>>>(ids, emb, pe, X, Xr);

    for (int l = 0; l < LL; l++) {
        gemm_tf32_nt<true, false, true, true><<<dim3(18, M / 128), 256, NT_SMEM>>>(
            M, 3 * Dd, Dd, Xr, Dd, Wqkv + (size_t)l * 3 * Dd * Dd, Dd,
            QKV, Dd, Bqkv + (size_t)l * 3 * Dd);

        flash_attn<<<dim3(Ss / 128, Bb * Hh), 256, FL_SMEM>>>(
            QKV, QKV + MOFF, QKV + 2 * MOFF, Hb);

        add_ln_kernel<<<M, 256>>>(X, Hb, L1g + l * Dd, L1b + l * Dd, Y1, Y1r, 0);

        gemm_tf32_nt<true, true, true, false><<<dim3(DFF / 128, M / 128), 256, NT_SMEM>>>(
            M, DFF, Dd, Y1r, Dd, W1r + (size_t)l * DFF * Dd, Dd, F, DFF, B1p + l * DFF);
        gemm_tf32_nt<true, false, false, false><<<dim3(Dd / 128, M / 128), 256, NT_SMEM>>>(
            M, Dd, DFF, F, DFF, W2r + (size_t)l * Dd * DFF, DFF, Hb, Dd, B2p + l * Dd);

        float* outp = (l == LL - 1) ? (float*)d_out : X;
        float* outr = (l == LL - 1) ? nullptr : Xr;
        add_ln_kernel<<<M, 256>>>(Y1, Hb, L2g + l * Dd, L2b + l * Dd, outp, outr, (l == LL - 1) ? 1 : 0);
    }
}

// round 8
// speedup vs baseline: 1.6084x; 1.0299x over previous
#include <cuda_runtime.h>
#include <math.h>

#define Bb   8
#define Ss   1024
#define Dd   768
#define Hh   12
#define HDh  64
#define DFF  3072
#define LL   6
#define MOFF (Bb*Ss*Dd)      // 6291456, size of one of Q/K/V

// ---------------- scratch (all activation/weight tensors in "P-layout":
// within each 32-aligned feature block, logical k stored at (k&3)*8 + (k>>2)) --------
__device__ float gX   [Bb*Ss*Dd];
__device__ float gXr  [Bb*Ss*Dd];
__device__ float gQKV [3*Bb*Ss*Dd];
__device__ float gHb  [Bb*Ss*Dd];
__device__ float gY1  [Bb*Ss*Dd];
__device__ float gY1r [Bb*Ss*Dd];
__device__ float gF   [Bb*Ss*DFF];
__device__ float gWqkv[LL*3*Dd*Dd];
__device__ float gBqkv[LL*3*Dd];
__device__ float gW1r [LL*DFF*Dd];
__device__ float gW2r [LL*Dd*DFF];
__device__ float gB1p [LL*DFF];
__device__ float gB2p [LL*Dd];
__device__ float gLn1g[LL*Dd];
__device__ float gLn1b[LL*Dd];
__device__ float gLn2g[LL*Dd];
__device__ float gLn2b[LL*Dd];

// ---------------- helpers ----------------
__device__ __forceinline__ int inv32(int j) { return ((j & 7) << 2) | (j >> 3); }

__device__ __forceinline__ float f2tf32f(float f) {
    unsigned u;
    asm("cvt.rna.tf32.f32 %0, %1;" : "=r"(u) : "f"(f));
    return __uint_as_float(u);
}
__device__ __forceinline__ unsigned f2tf32u(float f) {
    unsigned u;
    asm("cvt.rna.tf32.f32 %0, %1;" : "=r"(u) : "f"(f));
    return u;
}

__device__ __forceinline__ void mma_tf32(float c[4], unsigned a0, unsigned a1, unsigned a2, unsigned a3,
                                         unsigned b0, unsigned b1) {
    asm volatile(
        "mma.sync.aligned.m16n8k8.row.col.f32.tf32.tf32.f32 "
        "{%0,%1,%2,%3}, {%4,%5,%6,%7}, {%8,%9}, {%0,%1,%2,%3};\n"
        : "+f"(c[0]), "+f"(c[1]), "+f"(c[2]), "+f"(c[3])
        : "r"(a0), "r"(a1), "r"(a2), "r"(a3), "r"(b0), "r"(b1));
}

__device__ __forceinline__ void cp16(unsigned* smem_dst, const void* gmem_src) {
    unsigned s = (unsigned)__cvta_generic_to_shared(smem_dst);
    asm volatile("cp.async.cg.shared.global [%0], [%1], 16;\n" :: "r"(s), "l"(gmem_src));
}
#define CP_COMMIT asm volatile("cp.async.commit_group;\n" ::)
#define CP_WAIT0  asm volatile("cp.async.wait_group 0;\n" ::)

// ---------------- prep: permute+round weights, permute params ----------------
// grid (rowsPerL, LL), 256 threads; pure bitwise index math.
__global__ void perm_weight(float* __restrict__ dst, const float* __restrict__ src,
                            int cols, long dstL, long srcL) {
    const int l  = blockIdx.y;
    const int rp = blockIdx.x;
    const int r  = (rp & ~31) | inv32(rp & 31);
    const float* s = src + l * srcL + (long)r * cols;
    float* d       = dst + l * dstL + (long)rp * cols;
    for (int cp = threadIdx.x; cp < cols; cp += 256) {
        int c = (cp & ~31) | inv32(cp & 31);
        d[cp] = f2tf32f(s[c]);
    }
}

__global__ void perm_vec(float* __restrict__ dst, const float* __restrict__ src) {
    int i = blockIdx.x * blockDim.x + threadIdx.x;
    dst[i] = src[(i & ~31) | inv32(i & 31)];
}

__global__ void pack_qkv_b(float* __restrict__ dst, const float* __restrict__ bq,
                           const float* __restrict__ bk, const float* __restrict__ bv) {
    int i = blockIdx.x * blockDim.x + threadIdx.x;     // phys over LL*2304
    int pos = (i & ~31) | inv32(i & 31);
    int l = pos / 2304, n = pos % 2304;
    dst[i] = (n < 768) ? bq[l * 768 + n] : (n < 1536) ? bk[l * 768 + n - 768] : bv[l * 768 + n - 1536];
}

// ---------------- embedding (writes P-layout) ----------------
__global__ void embed_kernel(const int* __restrict__ ids, const float* __restrict__ emb,
                             const float* __restrict__ pe, float* __restrict__ x,
                             float* __restrict__ xr) {
    int i  = blockIdx.x * blockDim.x + threadIdx.x;
    int dp = i % Dd;
    int bs = i / Dd;
    int s  = bs % Ss;
    int d  = (dp & ~31) | inv32(dp & 31);
    float v = emb[(size_t)ids[bs] * Dd + d] + pe[(size_t)s * Dd + d];
    x[i]  = v;
    xr[i] = f2tf32f(v);
}

// ============ TF32 NT GEMM, cp.async double-buffered, ONE barrier per k-tile ============
// All operands in P-layout, pre-rounded. BM=128, BN=128, BK=32, 256 thr, 2 CTA/SM.
// Loop: WAIT0 -> sync -> ISSUE(i+1) -> COMPUTE(i). The single sync publishes buffer i
// AND proves all warps are past COMPUTE(i-1), so overwriting buffer (i+1)&1 is safe.
template<bool BIAS, bool RELU, bool ROUND, bool SPLIT>
__global__ __launch_bounds__(256, 2) void gemm_tf32_nt(
    int M, int N, int K,
    const float* __restrict__ A, int lda,
    const float* __restrict__ B, int ldb,
    float* __restrict__ C, int ldc,
    const float* __restrict__ bias)
{
    extern __shared__ unsigned sm[];
    const unsigned* Ap = (const unsigned*)(A + (size_t)(blockIdx.y * 128) * lda);
    const unsigned* Bp = (const unsigned*)(B + (size_t)(blockIdx.x * 128) * ldb);
    const int tid = threadIdx.x;
    const int lane = tid & 31, warp = tid >> 5;
    const int wm = (warp >> 2) * 64, wn = (warp & 3) * 32;
    const int grp = lane >> 2, tig = lane & 3;
    const int lrow = tid >> 3;            // 0..31
    const int lc4  = (tid & 7) * 4;       // 0..28

    float acc[4][4][4] = {};
    const int nk = K >> 5;

    auto ISSUE = [&](int i) {
        int k0 = i << 5;
        unsigned* base = sm + (i & 1) * 9216;
        #pragma unroll
        for (int p = 0; p < 4; p++) {
            int r = lrow + p * 32;
            cp16(base + r * 36 + lc4,        Ap + (size_t)r * lda + k0 + lc4);
            cp16(base + 4608 + r * 36 + lc4, Bp + (size_t)r * ldb + k0 + lc4);
        }
        CP_COMMIT;
    };

    ISSUE(0);
    for (int i = 0; i < nk; i++) {
        CP_WAIT0;
        __syncthreads();
        if (i + 1 < nk) ISSUE(i + 1);
        const unsigned* As = sm + (i & 1) * 9216;
        const unsigned* Bs = As + 4608;
        #pragma unroll
        for (int h = 0; h < 2; h++) {
            uint4 a0[4], a1[4];
            #pragma unroll
            for (int mi = 0; mi < 4; mi++) {
                int r = wm + mi * 16 + grp;
                a0[mi] = *(const uint4*)(As + r * 36 + tig * 8 + 4 * h);
                a1[mi] = *(const uint4*)(As + (r + 8) * 36 + tig * 8 + 4 * h);
            }
            #pragma unroll
            for (int ni = 0; ni < 4; ni++) {
                int nb = wn + ni * 8 + grp;
                uint4 bf = *(const uint4*)(Bs + nb * 36 + tig * 8 + 4 * h);
                #pragma unroll
                for (int mi = 0; mi < 4; mi++) {
                    mma_tf32(acc[mi][ni], a0[mi].x, a1[mi].x, a0[mi].y, a1[mi].y, bf.x, bf.y);
                    mma_tf32(acc[mi][ni], a0[mi].z, a1[mi].z, a0[mi].w, a1[mi].w, bf.z, bf.w);
                }
            }
        }
    }

    #pragma unroll
    for (int mi = 0; mi < 4; mi++) {
        int row = blockIdx.y * 128 + wm + mi * 16 + grp;
        #pragma unroll
        for (int ni = 0; ni < 4; ni++) {
            int colg = blockIdx.x * 128 + wn + ni * 8 + 2 * tig;   // phys col
            float* Cp;
            int col;
            if (SPLIT) {
                int qsel = blockIdx.x / 6;
                Cp = C + (size_t)qsel * MOFF;
                col = colg - qsel * 768;
            } else {
                Cp = C;
                col = colg;
            }
            float b0 = 0.f, b1 = 0.f;
            if (BIAS) { b0 = bias[colg]; b1 = bias[colg + 1]; }
            float v0 = acc[mi][ni][0] + b0;
            float v1 = acc[mi][ni][1] + b1;
            float v2 = acc[mi][ni][2] + b0;
            float v3 = acc[mi][ni][3] + b1;
            if (RELU)  { v0 = fmaxf(v0, 0.f); v1 = fmaxf(v1, 0.f); v2 = fmaxf(v2, 0.f); v3 = fmaxf(v3, 0.f); }
            if (ROUND) { v0 = f2tf32f(v0); v1 = f2tf32f(v1); v2 = f2tf32f(v2); v3 = f2tf32f(v3); }
            *(float2*)(Cp + (size_t)row * ldc + col)       = make_float2(v0, v1);
            *(float2*)(Cp + (size_t)(row + 8) * ldc + col) = make_float2(v2, v3);
        }
    }
}

// ============ Flash attention (Q/K/V in P-layout along head-dim) ============
#define FL_SMEM (27648 * 4)
__global__ __launch_bounds__(256, 1) void flash_attn(
    const float* __restrict__ Qg, const float* __restrict__ Kg,
    const float* __restrict__ Vg, float* __restrict__ Og)
{
    extern __shared__ unsigned sm[];
    unsigned* Qs = sm;                      // [2][128*36]
    unsigned* Ks = sm + 2 * 128 * 36;       // [2][64*36]
    unsigned* Vs = Ks + 2 * 64 * 36;        // [2][64*36]
    unsigned* Ps = Vs + 2 * 64 * 36;        // [2][128*36]

    const int bh = blockIdx.y;
    const int qbase = blockIdx.x * 128;
    const unsigned* Qp = (const unsigned*)(Qg + (size_t)bh * Ss * HDh + (size_t)qbase * HDh);
    const unsigned* Kp = (const unsigned*)(Kg + (size_t)bh * Ss * HDh);
    const unsigned* Vp = (const unsigned*)(Vg + (size_t)bh * Ss * HDh);

    const int tid = threadIdx.x, lane = tid & 31, warp = tid >> 5;
    const int grp = lane >> 2, tig = lane & 3;
    const int wq = warp * 16;

    // Q tile -> Qs (verbatim: global already permuted)
    #pragma unroll
    for (int p = 0; p < 8; p++) {
        int i = tid + p * 256;
        int row = i >> 4, f = i & 15;
        uint4 v = *(const uint4*)(Qp + (size_t)row * 64 + f * 4);
        *(uint4*)(Qs + (f >> 3) * 128 * 36 + row * 36 + (f & 7) * 4) = v;
    }
    __syncthreads();

    uint4 qf[2][2][2];
    #pragma unroll
    for (int s = 0; s < 2; s++) {
        const unsigned* q = Qs + s * 128 * 36;
        #pragma unroll
        for (int rh = 0; rh < 2; rh++) {
            int r = wq + grp + rh * 8;
            qf[s][rh][0] = *(const uint4*)(q + r * 36 + tig * 8);
            qf[s][rh][1] = *(const uint4*)(q + r * 36 + tig * 8 + 4);
        }
    }

    float oa[8][4];
    #pragma unroll
    for (int ni = 0; ni < 8; ni++) { oa[ni][0]=0.f; oa[ni][1]=0.f; oa[ni][2]=0.f; oa[ni][3]=0.f; }
    float m0 = -1e30f, m1 = -1e30f, l0 = 0.f, l1 = 0.f;

    for (int kv0 = 0; kv0 < Ss; kv0 += 64) {
        __syncthreads();
        #pragma unroll
        for (int p = 0; p < 4; p++) {
            int i = tid + p * 256;
            int row = i >> 4, f = i & 15;
            uint4 v = *(const uint4*)(Kp + (size_t)(kv0 + row) * 64 + f * 4);
            *(uint4*)(Ks + (f >> 3) * 64 * 36 + row * 36 + (f & 7) * 4) = v;
        }
        {
            int c = tid >> 6;
            int n = tid & 63;                 // phys head-dim column
            #pragma unroll
            for (int s = 0; s < 2; s++) {
                unsigned vb[8];
                #pragma unroll
                for (int t = 0; t < 8; t++)
                    vb[t] = Vp[(size_t)(kv0 + s * 32 + c + 4 * t) * 64 + n];
                unsigned* dst = Vs + s * 64 * 36 + n * 36 + c * 8;
                *(uint4*)(dst)     = make_uint4(vb[0], vb[1], vb[2], vb[3]);
                *(uint4*)(dst + 4) = make_uint4(vb[4], vb[5], vb[6], vb[7]);
            }
        }
        __syncthreads();

        float sacc[8][4];
        #pragma unroll
        for (int ni = 0; ni < 8; ni++) { sacc[ni][0]=0.f; sacc[ni][1]=0.f; sacc[ni][2]=0.f; sacc[ni][3]=0.f; }
        #pragma unroll
        for (int s = 0; s < 2; s++) {
            const unsigned* kb = Ks + s * 64 * 36;
            #pragma unroll
            for (int h = 0; h < 2; h++) {
                #pragma unroll
                for (int ni = 0; ni < 8; ni++) {
                    int nb = ni * 8 + grp;
                    uint4 bf = *(const uint4*)(kb + nb * 36 + tig * 8 + 4 * h);
                    mma_tf32(sacc[ni], qf[s][0][h].x, qf[s][1][h].x, qf[s][0][h].y, qf[s][1][h].y, bf.x, bf.y);
                    mma_tf32(sacc[ni], qf[s][0][h].z, qf[s][1][h].z, qf[s][0][h].w, qf[s][1][h].w, bf.z, bf.w);
                }
            }
        }

        float mx0 = -1e30f, mx1 = -1e30f;
        #pragma unroll
        for (int ni = 0; ni < 8; ni++) {
            sacc[ni][0] *= 0.125f; sacc[ni][1] *= 0.125f; sacc[ni][2] *= 0.125f; sacc[ni][3] *= 0.125f;
            mx0 = fmaxf(mx0, fmaxf(sacc[ni][0], sacc[ni][1]));
            mx1 = fmaxf(mx1, fmaxf(sacc[ni][2], sacc[ni][3]));
        }
        mx0 = fmaxf(mx0, __shfl_xor_sync(0xffffffffu, mx0, 1));
        mx0 = fmaxf(mx0, __shfl_xor_sync(0xffffffffu, mx0, 2));
        mx1 = fmaxf(mx1, __shfl_xor_sync(0xffffffffu, mx1, 1));
        mx1 = fmaxf(mx1, __shfl_xor_sync(0xffffffffu, mx1, 2));
        float mn0 = fmaxf(m0, mx0), mn1 = fmaxf(m1, mx1);
        float al0 = __expf(m0 - mn0), al1 = __expf(m1 - mn1);
        float sum0 = 0.f, sum1 = 0.f;
        {
            int r0 = wq + grp, r1 = r0 + 8;
            #pragma unroll
            for (int ni = 0; ni < 8; ni++) {
                float p0 = __expf(sacc[ni][0] - mn0);
                float p1 = __expf(sacc[ni][1] - mn0);
                float p2 = __expf(sacc[ni][2] - mn1);
                float p3 = __expf(sacc[ni][3] - mn1);
                sum0 += p0 + p1; sum1 += p2 + p3;
                int j  = ni * 8 + 2 * tig;
                int sub = j >> 5, jj = j & 31;
                unsigned* pp = Ps + sub * 128 * 36;
                int s0 = (jj & 3) * 8 + (jj >> 2);
                int s1 = ((jj + 1) & 3) * 8 + ((jj + 1) >> 2);
                pp[r0 * 36 + s0] = f2tf32u(p0);
                pp[r0 * 36 + s1] = f2tf32u(p1);
                pp[r1 * 36 + s0] = f2tf32u(p2);
                pp[r1 * 36 + s1] = f2tf32u(p3);
            }
        }
        sum0 += __shfl_xor_sync(0xffffffffu, sum0, 1);
        sum0 += __shfl_xor_sync(0xffffffffu, sum0, 2);
        sum1 += __shfl_xor_sync(0xffffffffu, sum1, 1);
        sum1 += __shfl_xor_sync(0xffffffffu, sum1, 2);
        l0 = l0 * al0 + sum0;  l1 = l1 * al1 + sum1;
        m0 = mn0;  m1 = mn1;
        #pragma unroll
        for (int ni = 0; ni < 8; ni++) {
            oa[ni][0] *= al0; oa[ni][1] *= al0; oa[ni][2] *= al1; oa[ni][3] *= al1;
        }
        __syncwarp();

        uint4 pf[2][2][2];
        #pragma unroll
        for (int s = 0; s < 2; s++) {
            const unsigned* p = Ps + s * 128 * 36;
            #pragma unroll
            for (int rh = 0; rh < 2; rh++) {
                int r = wq + grp + rh * 8;
                pf[s][rh][0] = *(const uint4*)(p + r * 36 + tig * 8);
                pf[s][rh][1] = *(const uint4*)(p + r * 36 + tig * 8 + 4);
            }
        }
        #pragma unroll
        for (int s = 0; s < 2; s++) {
            const unsigned* vbp = Vs + s * 64 * 36;
            #pragma unroll
            for (int h = 0; h < 2; h++) {
                #pragma unroll
                for (int ni = 0; ni < 8; ni++) {
                    int nb = ni * 8 + grp;
                    uint4 bf = *(const uint4*)(vbp + nb * 36 + tig * 8 + 4 * h);
                    mma_tf32(oa[ni], pf[s][0][h].x, pf[s][1][h].x, pf[s][0][h].y, pf[s][1][h].y, bf.x, bf.y);
                    mma_tf32(oa[ni], pf[s][0][h].z, pf[s][1][h].z, pf[s][0][h].w, pf[s][1][h].w, bf.z, bf.w);
                }
            }
        }
    }

    float i0 = 1.f / l0, i1 = 1.f / l1;
    const int b = bh / Hh, h = bh % Hh;
    float* Op = Og + (size_t)b * Ss * Dd + (size_t)qbase * Dd + h * HDh;
    int r0 = wq + grp;
    #pragma unroll
    for (int ni = 0; ni < 8; ni++) {
        int col = ni * 8 + 2 * tig;          // phys head-dim
        *(float2*)(Op + (size_t)r0 * Dd + col)       = make_float2(oa[ni][0] * i0, oa[ni][1] * i0);
        *(float2*)(Op + (size_t)(r0 + 8) * Dd + col) = make_float2(oa[ni][2] * i1, oa[ni][3] * i1);
    }
}

// ---------------- add + layernorm: warp-per-row, shfl-only reductions ----------------
// 256 threads = 8 warps = 8 rows/block; 192 float4 per row, lane j covers idx4 = lane + j*32.
__global__ __launch_bounds__(256) void add_ln_kernel(
    const float* __restrict__ x, const float* __restrict__ h,
    const float* __restrict__ g, const float* __restrict__ bias,
    float* __restrict__ out, float* __restrict__ outr, int unperm)
{
    const int lane = threadIdx.x & 31, warp = threadIdx.x >> 5;
    const size_t row = (size_t)blockIdx.x * 8 + warp;
    const float4* px = (const float4*)(x + row * Dd);
    const float4* ph = (const float4*)(h + row * Dd);
    const float4* pg = (const float4*)g;
    const float4* pb = (const float4*)bias;

    float4 v[6];
    float s = 0.f;
    #pragma unroll
    for (int j = 0; j < 6; j++) {
        int i4 = lane + j * 32;
        float4 a = px[i4], b = ph[i4];
        v[j] = make_float4(a.x + b.x, a.y + b.y, a.z + b.z, a.w + b.w);
        s += v[j].x + v[j].y + v[j].z + v[j].w;
    }
    #pragma unroll
    for (int o = 16; o > 0; o >>= 1) s += __shfl_xor_sync(0xffffffffu, s, o);
    float mu = s * (1.f / Dd);

    float q = 0.f;
    #pragma unroll
    for (int j = 0; j < 6; j++) {
        float dx = v[j].x - mu, dy = v[j].y - mu, dz = v[j].z - mu, dw = v[j].w - mu;
        q += dx * dx + dy * dy + dz * dz + dw * dw;
    }
    #pragma unroll
    for (int o = 16; o > 0; o >>= 1) q += __shfl_xor_sync(0xffffffffu, q, o);
    float inv = rsqrtf(q * (1.f / Dd) + 1e-5f);

    float* po = out + row * Dd;
    float* pr = outr ? outr + row * Dd : nullptr;
    #pragma unroll
    for (int j = 0; j < 6; j++) {
        int i4 = lane + j * 32;
        float4 gg = pg[i4], bb = pb[i4];
        float o0 = (v[j].x - mu) * inv * gg.x + bb.x;
        float o1 = (v[j].y - mu) * inv * gg.y + bb.y;
        float o2 = (v[j].z - mu) * inv * gg.z + bb.z;
        float o3 = (v[j].w - mu) * inv * gg.w + bb.w;
        if (unperm) {
            int c = i4 * 4;
            po[(c & ~31) | inv32(c & 31)]             = o0;
            po[((c+1) & ~31) | inv32((c+1) & 31)]     = o1;
            po[((c+2) & ~31) | inv32((c+2) & 31)]     = o2;
            po[((c+3) & ~31) | inv32((c+3) & 31)]     = o3;
        } else {
            ((float4*)po)[i4] = make_float4(o0, o1, o2, o3);
        }
        if (pr)
            ((float4*)pr)[i4] = make_float4(f2tf32f(o0), f2tf32f(o1), f2tf32f(o2), f2tf32f(o3));
    }
}

// ---------------- host launcher ----------------
extern "C" void kernel_launch(void* const* d_in, const int* in_sizes, int n_in,
                              void* d_out, int out_size) {
    const int*   ids  = (const int*)  d_in[0];
    const float* emb  = (const float*)d_in[1];
    const float* pe   = (const float*)d_in[2];
    const float* Wq   = (const float*)d_in[3];
    const float* bq   = (const float*)d_in[4];
    const float* Wk   = (const float*)d_in[5];
    const float* bk   = (const float*)d_in[6];
    const float* Wv   = (const float*)d_in[7];
    const float* bv   = (const float*)d_in[8];
    const float* W1   = (const float*)d_in[9];
    const float* b1   = (const float*)d_in[10];
    const float* W2   = (const float*)d_in[11];
    const float* b2   = (const float*)d_in[12];
    const float* ln1g = (const float*)d_in[13];
    const float* ln1b = (const float*)d_in[14];
    const float* ln2g = (const float*)d_in[15];
    const float* ln2b = (const float*)d_in[16];

    float *X, *Xr, *QKV, *Hb, *Y1, *Y1r, *F, *Wqkv, *Bqkv, *W1r, *W2r;
    float *B1p, *B2p, *L1g, *L1b, *L2g, *L2b;
    cudaGetSymbolAddress((void**)&X,    gX);
    cudaGetSymbolAddress((void**)&Xr,   gXr);
    cudaGetSymbolAddress((void**)&QKV,  gQKV);
    cudaGetSymbolAddress((void**)&Hb,   gHb);
    cudaGetSymbolAddress((void**)&Y1,   gY1);
    cudaGetSymbolAddress((void**)&Y1r,  gY1r);
    cudaGetSymbolAddress((void**)&F,    gF);
    cudaGetSymbolAddress((void**)&Wqkv, gWqkv);
    cudaGetSymbolAddress((void**)&Bqkv, gBqkv);
    cudaGetSymbolAddress((void**)&W1r,  gW1r);
    cudaGetSymbolAddress((void**)&W2r,  gW2r);
    cudaGetSymbolAddress((void**)&B1p,  gB1p);
    cudaGetSymbolAddress((void**)&B2p,  gB2p);
    cudaGetSymbolAddress((void**)&L1g,  gLn1g);
    cudaGetSymbolAddress((void**)&L1b,  gLn1b);
    cudaGetSymbolAddress((void**)&L2g,  gLn2g);
    cudaGetSymbolAddress((void**)&L2b,  gLn2b);

    const int NT_SMEM = 2 * 9216 * 4;   // 73728 B
    cudaFuncSetAttribute(gemm_tf32_nt<true,  false, true,  true >, cudaFuncAttributeMaxDynamicSharedMemorySize, NT_SMEM);
    cudaFuncSetAttribute(gemm_tf32_nt<true,  true,  true,  false>, cudaFuncAttributeMaxDynamicSharedMemorySize, NT_SMEM);
    cudaFuncSetAttribute(gemm_tf32_nt<true,  false, false, false>, cudaFuncAttributeMaxDynamicSharedMemorySize, NT_SMEM);
    cudaFuncSetAttribute(flash_attn, cudaFuncAttributeMaxDynamicSharedMemorySize, FL_SMEM);

    const int M = Bb * Ss;   // 8192

    // prep: permute+round weights, permute biases/params
    perm_weight<<<dim3(768, LL), 256>>>(Wqkv,            Wq, 768, 2304L*768, 768L*768);
    perm_weight<<<dim3(768, LL), 256>>>(Wqkv + 768*768,  Wk, 768, 2304L*768, 768L*768);
    perm_weight<<<dim3(768, LL), 256>>>(Wqkv + 1536*768, Wv, 768, 2304L*768, 768L*768);
    perm_weight<<<dim3(DFF, LL), 256>>>(W1r,             W1, 768, (long)DFF*768, (long)DFF*768);
    perm_weight<<<dim3(768, LL), 256>>>(W2r,             W2, DFF, 768L*DFF, 768L*DFF);
    pack_qkv_b<<<(LL * 2304) / 256, 256>>>(Bqkv, bq, bk, bv);
    perm_vec<<<(LL * DFF) / 256, 256>>>(B1p, b1);
    perm_vec<<<(LL * Dd)  / 256, 256>>>(B2p, b2);
    perm_vec<<<(LL * Dd)  / 256, 256>>>(L1g, ln1g);
    perm_vec<<<(LL * Dd)  / 256, 256>>>(L1b, ln1b);
    perm_vec<<<(LL * Dd)  / 256, 256>>>(L2g, ln2g);
    perm_vec<<<(LL * Dd)  / 256, 256>>>(L2b, ln2b);

    embed_kernel<<<(Bb * Ss * Dd) / 256, 256>>>(ids, emb, pe, X, Xr);

    for (int l = 0; l < LL; l++) {
        gemm_tf32_nt<true, false, true, true><<<dim3(18, M / 128), 256, NT_SMEM>>>(
            M, 3 * Dd, Dd, Xr, Dd, Wqkv + (size_t)l * 3 * Dd * Dd, Dd,
            QKV, Dd, Bqkv + (size_t)l * 3 * Dd);

        flash_attn<<<dim3(Ss / 128, Bb * Hh), 256, FL_SMEM>>>(
            QKV, QKV + MOFF, QKV + 2 * MOFF, Hb);

        add_ln_kernel<<<M / 8, 256>>>(X, Hb, L1g + l * Dd, L1b + l * Dd, Y1, Y1r, 0);

        gemm_tf32_nt<true, true, true, false><<<dim3(DFF / 128, M / 128), 256, NT_SMEM>>>(
            M, DFF, Dd, Y1r, Dd, W1r + (size_t)l * DFF * Dd, Dd, F, DFF, B1p + l * DFF);
        gemm_tf32_nt<true, false, false, false><<<dim3(Dd / 128, M / 128), 256, NT_SMEM>>>(
            M, Dd, DFF, F, DFF, W2r + (size_t)l * Dd * DFF, DFF, Hb, Dd, B2p + l * Dd);

        float* outp = (l == LL - 1) ? (float*)d_out : X;
        float* outr = (l == LL - 1) ? nullptr : Xr;
        add_ln_kernel<<<M / 8, 256>>>(Y1, Hb, L2g + l * Dd, L2b + l * Dd, outp, outr, (l == LL - 1) ? 1 : 0);
    }
}